// round 1
// baseline (speedup 1.0000x reference)
#include <cuda_runtime.h>
#include <math.h>

#define NT     2048
#define NB     32
#define ND     64
#define OUT_T  2144
#define KTOP   8

// Scratch (allocation-free: __device__ globals)
__device__ float  g_xt[NB * ND * NT];          // transposed input (b,d,t), 16 MB
__device__ float4 g_comps[NB * ND * KTOP];     // per-series {k, A=re/1024, B=im/1024, _}
__device__ float2 g_rot[2048];                 // e^{+2*pi*i*j/2048}

// ---------------------------------------------------------------------------
// Kernel A: transpose (b,t,d) -> (b,d,t); block 0 also builds the rotation table
// ---------------------------------------------------------------------------
__global__ void k_transpose(const float* __restrict__ x) {
    __shared__ float tile[32][33];
    int b  = blockIdx.z;
    int d0 = blockIdx.x << 5;
    int t0 = blockIdx.y << 5;
    int tx = threadIdx.x, ty = threadIdx.y;

    const float* src = x + ((size_t)b * NT + t0) * ND + d0;
#pragma unroll
    for (int i = ty; i < 32; i += 8)
        tile[i][tx] = src[(size_t)i * ND + tx];
    __syncthreads();

    float* dst = g_xt + ((size_t)b * ND + d0) * NT + t0;
#pragma unroll
    for (int i = ty; i < 32; i += 8)
        dst[(size_t)i * NT + tx] = tile[tx][i];

    if (blockIdx.x == 0 && blockIdx.y == 0 && blockIdx.z == 0) {
        int tid = ty * 32 + tx;
        for (int j = tid; j < 2048; j += 256) {
            // double-precision table build (one-time, 2048 entries): table exact to fp32 rounding
            double ang = 6.283185307179586476925287 * (double)j / 2048.0;
            double s, c;
            sincos(ang, &s, &c);
            g_rot[j] = make_float2((float)c, (float)s);
        }
    }
}

// ---------------------------------------------------------------------------
// Kernel B: per-series 2048-pt radix-2 DIF FFT in smem + warp top-8 by |X|^2
// One series per block (256 threads). Output left bit-reversed; true k recovered
// via 11-bit bit reversal. Candidates k in [1,1023] <=> even positions != 0.
// ---------------------------------------------------------------------------
__global__ void k_fft_topk() {
    __shared__ float2 X[NT];        // 16 KB
    __shared__ float2 W[NT / 2];    //  8 KB, W[j] = e^{-2*pi*i*j/2048}
    int tid  = threadIdx.x;
    int sidx = blockIdx.x;          // b*64 + d

    const float* src = g_xt + (size_t)sidx * NT;
    for (int i = tid; i < NT; i += 256)
        X[i] = make_float2(src[i], 0.0f);
    for (int j = tid; j < NT / 2; j += 256) {
        float2 r = g_rot[j];
        W[j] = make_float2(r.x, -r.y);   // conj
    }
    __syncthreads();

#pragma unroll
    for (int hb = 10; hb >= 0; hb--) {
        int half = 1 << hb;
#pragma unroll
        for (int it = 0; it < 4; it++) {
            int idx = tid + (it << 8);              // 0..1023
            int j   = idx & (half - 1);
            int i0  = ((idx >> hb) << (hb + 1)) | j;
            int i1  = i0 + half;
            float2 a  = X[i0];
            float2 bb = X[i1];
            float2 w  = W[j << (10 - hb)];
            X[i0] = make_float2(a.x + bb.x, a.y + bb.y);
            float dr = a.x - bb.x, di = a.y - bb.y;
            X[i1] = make_float2(dr * w.x - di * w.y, dr * w.y + di * w.x);
        }
        __syncthreads();
    }

    // warp 0: top-8 over the 1023 candidate bins
    if (tid < 32) {
        int lane = tid;
        float bv[KTOP];
        int   bp[KTOP];
#pragma unroll
        for (int q = 0; q < KTOP; q++) { bv[q] = -1.0f; bp[q] = 0; }

        for (int m = lane; m < 1024; m += 32) {
            if (m == 0) continue;                   // skip DC
            float2 v = X[2 * m];                    // even pos <=> k in [1,1023]
            float mg = fmaf(v.x, v.x, v.y * v.y);
            if (mg > bv[KTOP - 1]) {
                bv[KTOP - 1] = mg; bp[KTOP - 1] = 2 * m;
#pragma unroll
                for (int q = KTOP - 1; q > 0; q--) {
                    if (bv[q] > bv[q - 1]) {
                        float tv = bv[q]; bv[q] = bv[q - 1]; bv[q - 1] = tv;
                        int   tp = bp[q]; bp[q] = bp[q - 1]; bp[q - 1] = tp;
                    }
                }
            }
        }

        // 8 rounds of warp arg-max merge
        for (int r = 0; r < KTOP; r++) {
            float v = bv[0];
            int bestl = lane;
#pragma unroll
            for (int off = 16; off; off >>= 1) {
                float ov = __shfl_xor_sync(0xffffffffu, v, off);
                int   ol = __shfl_xor_sync(0xffffffffu, bestl, off);
                if (ov > v || (ov == v && ol < bestl)) { v = ov; bestl = ol; }
            }
            int wpos = __shfl_sync(0xffffffffu, bp[0], bestl);
            if (lane == bestl) {
#pragma unroll
                for (int q = 0; q < KTOP - 1; q++) { bv[q] = bv[q + 1]; bp[q] = bp[q + 1]; }
                bv[KTOP - 1] = -1.0f;
            }
            if (lane == 0) {
                int k = (int)(__brev((unsigned)wpos) >> 21);   // 11-bit bit-reverse
                float2 xv = X[wpos];
                // conj pair folded: contribution = 2/T * (re*cos - im*sin)
                g_comps[sidx * KTOP + r] =
                    make_float4((float)k, xv.x * (1.0f / 1024.0f), xv.y * (1.0f / 1024.0f), 0.0f);
            }
        }
    }
}

// ---------------------------------------------------------------------------
// Kernel C: synthesis via exact-period complex rotation (no cos/MUFU in loop)
// out[b,tt,d] = sum_j Re{ (A_j + i B_j) * e^{+2*pi*i*k_j*tt/2048} }
// Thread = (d, tt-chunk of 32). Seed from table at (k*tt0 mod 2048), step by table[k].
// ---------------------------------------------------------------------------
__global__ void k_synth(float* __restrict__ out) {
    __shared__ float4 sp[ND * KTOP];   // 8 KB
    __shared__ float2 srot[2048];      // 16 KB
    int tid = threadIdx.x;
    int b   = blockIdx.y;

    for (int i = tid; i < ND * KTOP; i += 256)
        sp[i] = g_comps[b * ND * KTOP + i];
    for (int i = tid; i < 2048; i += 256)
        srot[i] = g_rot[i];
    __syncthreads();

    int d   = tid & 63;
    int tt0 = blockIdx.x * 128 + (tid >> 6) * 32;
    if (tt0 >= OUT_T) return;
    int nt = OUT_T - tt0;
    if (nt > 32) nt = 32;

    float vr[8], vi[8], wr[8], wi[8];
#pragma unroll
    for (int j = 0; j < 8; j++) {
        float4 c = sp[d * 8 + j];
        int k = (int)c.x;
        float2 w = srot[k];
        wr[j] = w.x; wi[j] = w.y;
        float2 t0v = srot[(k * tt0) & 2047];
        vr[j] = c.y * t0v.x - c.z * t0v.y;
        vi[j] = c.y * t0v.y + c.z * t0v.x;
    }

    float* op = out + ((size_t)b * OUT_T + tt0) * ND + d;
    for (int c = 0; c < nt; c++) {
        float s = ((vr[0] + vr[1]) + (vr[2] + vr[3])) +
                  ((vr[4] + vr[5]) + (vr[6] + vr[7]));
        op[(size_t)c * ND] = s;
#pragma unroll
        for (int j = 0; j < 8; j++) {
            float nr = vr[j] * wr[j] - vi[j] * wi[j];
            float ni = vr[j] * wi[j] + vi[j] * wr[j];
            vr[j] = nr; vi[j] = ni;
        }
    }
}

// ---------------------------------------------------------------------------
extern "C" void kernel_launch(void* const* d_in, const int* in_sizes, int n_in,
                              void* d_out, int out_size) {
    const float* x = (const float*)d_in[0];
    float* out = (float*)d_out;

    k_transpose<<<dim3(2, 64, 32), dim3(32, 8)>>>(x);
    k_fft_topk<<<NB * ND, 256>>>();
    k_synth<<<dim3(17, NB), 256>>>(out);
}

// round 2
// speedup vs baseline: 1.1671x; 1.1671x over previous
#include <cuda_runtime.h>
#include <math.h>

#define NT     2048
#define NB     32
#define ND     64
#define OUT_T  2144
#define KTOP   8

// Scratch (allocation-free: __device__ globals)
__device__ float  g_xt[NB * ND * NT];          // transposed input (b,d,t), 16 MB
__device__ float4 g_comps[NB * ND * KTOP];     // per-series {k, A, B, 2cos(w)}
__device__ float2 g_rot[2048];                 // e^{+2*pi*i*j/2048}

// ---------------------------------------------------------------------------
// Kernel A: transpose (b,t,d) -> (b,d,t), 64x64 tiles, float4 both directions.
// Block (0,0) also builds the rotation table.
// ---------------------------------------------------------------------------
__global__ void k_transpose(const float* __restrict__ x) {
    __shared__ float tile[64][65];
    int b  = blockIdx.y;
    int t0 = blockIdx.x << 6;
    int tid = threadIdx.x;
    int tx = tid & 15;          // float4 column within row
    int ty = tid >> 4;          // 0..15

    const float4* src = (const float4*)(x + ((size_t)b * NT + t0) * ND);
#pragma unroll
    for (int i = 0; i < 4; i++) {
        int r = ty + (i << 4);                 // t within tile
        float4 v = src[r * 16 + tx];
        tile[r][tx * 4 + 0] = v.x;
        tile[r][tx * 4 + 1] = v.y;
        tile[r][tx * 4 + 2] = v.z;
        tile[r][tx * 4 + 3] = v.w;
    }
    __syncthreads();
#pragma unroll
    for (int i = 0; i < 4; i++) {
        int d = ty + (i << 4);                 // full d dimension (ND=64)
        int c = tx * 4;                        // t within tile
        float4 v = make_float4(tile[c][d], tile[c + 1][d], tile[c + 2][d], tile[c + 3][d]);
        *(float4*)(g_xt + ((size_t)(b * ND + d)) * NT + t0 + c) = v;
    }

    if (blockIdx.x == 0 && blockIdx.y == 0) {
        for (int j = tid; j < 2048; j += 256) {
            double ang = 6.283185307179586476925287 * (double)j / 2048.0;
            double s, c;
            sincos(ang, &s, &c);
            g_rot[j] = make_float2((float)c, (float)s);
        }
    }
}

// ---------------------------------------------------------------------------
// Kernel B: packed-real-pair 2048-pt FFT (fused radix-4 passes + radix-8 tail)
// One block = two real series (d even/odd packed as complex). Output is
// bit-reversed (identical placement to the radix-2 DIF sequence).
// Warp 0/1 then do Hermitian unpack + top-8 for the even/odd series.
// ---------------------------------------------------------------------------
__device__ __forceinline__ float2 cadd(float2 a, float2 b) { return make_float2(a.x + b.x, a.y + b.y); }
__device__ __forceinline__ float2 csub(float2 a, float2 b) { return make_float2(a.x - b.x, a.y - b.y); }
__device__ __forceinline__ float2 cmul(float2 a, float2 b) {
    return make_float2(a.x * b.x - a.y * b.y, a.x * b.y + a.y * b.x);
}

__global__ void k_fft_topk() {
    __shared__ float2 X[NT];        // 16 KB
    __shared__ float2 W[512];       //  4 KB, W[m] = e^{-2*pi*i*m/2048}
    int tid  = threadIdx.x;
    int p    = blockIdx.x;          // pair index: b*32 + dp
    int b    = p >> 5;
    int dp   = p & 31;

    const float4* se = (const float4*)(g_xt + ((size_t)(b * ND + 2 * dp))     * NT);
    const float4* so = (const float4*)(g_xt + ((size_t)(b * ND + 2 * dp + 1)) * NT);
#pragma unroll
    for (int i = 0; i < 2; i++) {
        int idx = tid + (i << 8);              // 0..511 (float4 granularity)
        float4 e = se[idx];
        float4 o = so[idx];
        X[4 * idx + 0] = make_float2(e.x, o.x);
        X[4 * idx + 1] = make_float2(e.y, o.y);
        X[4 * idx + 2] = make_float2(e.z, o.z);
        X[4 * idx + 3] = make_float2(e.w, o.w);
    }
    for (int j = tid; j < 512; j += 256) {
        float2 r = g_rot[j];
        W[j] = make_float2(r.x, -r.y);
    }
    __syncthreads();

    // Fused radix-4 stages: lh = first-stage hb of each pair -> (10,9),(8,7),(6,5),(4,3)
#pragma unroll
    for (int lh = 10; lh >= 4; lh -= 2) {
        int hh = 1 << (lh - 1);                // quarter stride
#pragma unroll
        for (int it = 0; it < 2; it++) {
            int bi = tid + (it << 8);          // butterfly id 0..511
            int j  = bi & (hh - 1);
            int i0 = ((bi >> (lh - 1)) << (lh + 1)) | j;
            float2 w1 = W[j << (10 - lh)];
            float2 w2 = make_float2(w1.x * w1.x - w1.y * w1.y, 2.0f * w1.x * w1.y);
            float2 wm = make_float2(w1.y, -w1.x);              // -i * w1
            float2 a = X[i0], bb = X[i0 + hh], c = X[i0 + 2 * hh], d = X[i0 + 3 * hh];
            float2 s0 = cadd(a, c);
            float2 s2 = cmul(csub(a, c), w1);
            float2 s1 = cadd(bb, d);
            float2 s3 = cmul(csub(bb, d), wm);
            X[i0]          = cadd(s0, s1);
            X[i0 + hh]     = cmul(csub(s0, s1), w2);
            X[i0 + 2 * hh] = cadd(s2, s3);
            X[i0 + 3 * hh] = cmul(csub(s2, s3), w2);
        }
        __syncthreads();
    }

    // Superstage: fused radix-4 (hb 2,1) + final radix-2 (hb 0) on 8 consecutive
    // points per thread (base = tid*8), all in registers.
    {
        int base = tid << 3;
        float2 v[8];
        float4* Xv = (float4*)(X + base);
#pragma unroll
        for (int q = 0; q < 4; q++) {
            float4 t = Xv[q];
            v[2 * q]     = make_float2(t.x, t.y);
            v[2 * q + 1] = make_float2(t.z, t.w);
        }
        float2 w1_1 = W[256];                                  // e^{-i*pi/4}
#pragma unroll
        for (int j = 0; j < 2; j++) {
            float2 w1 = (j == 0) ? make_float2(1.0f, 0.0f) : w1_1;
            float2 w2 = make_float2(w1.x * w1.x - w1.y * w1.y, 2.0f * w1.x * w1.y);
            float2 wm = make_float2(w1.y, -w1.x);
            float2 a = v[j], bb = v[j + 2], c = v[j + 4], d = v[j + 6];
            float2 s0 = cadd(a, c);
            float2 s2 = cmul(csub(a, c), w1);
            float2 s1 = cadd(bb, d);
            float2 s3 = cmul(csub(bb, d), wm);
            v[j]     = cadd(s0, s1);
            v[j + 2] = cmul(csub(s0, s1), w2);
            v[j + 4] = cadd(s2, s3);
            v[j + 6] = cmul(csub(s2, s3), w2);
        }
        // final radix-2 (twiddle = 1) on consecutive pairs
#pragma unroll
        for (int q = 0; q < 4; q++) {
            float2 a = v[2 * q], bb = v[2 * q + 1];
            Xv[q] = make_float4(a.x + bb.x, a.y + bb.y, a.x - bb.x, a.y - bb.y);
        }
    }
    __syncthreads();

    // Hermitian unpack + top-8. Warp 0 -> even series, warp 1 -> odd series.
    if (tid < 64) {
        int w    = tid >> 5;
        int lane = tid & 31;
        float bv[KTOP];
        int   bk[KTOP];
#pragma unroll
        for (int q = 0; q < KTOP; q++) { bv[q] = -1.0f; bk[q] = 1; }

        for (int it = 0; it < 32; it++) {
            int k = 1 + lane + 32 * it;
            if (k >= 1024) break;
            int p1 = (int)(__brev((unsigned)k) >> 21);
            int p2 = (int)(__brev((unsigned)(2048 - k)) >> 21);
            float2 z1 = X[p1];
            float2 z2 = X[p2];
            float mg;
            if (w == 0) {
                float er = z1.x + z2.x, ei = z1.y - z2.y;
                mg = fmaf(er, er, ei * ei);
            } else {
                float orr = z1.y + z2.y, oi = z2.x - z1.x;
                mg = fmaf(orr, orr, oi * oi);
            }
            if (mg > bv[KTOP - 1]) {
                bv[KTOP - 1] = mg; bk[KTOP - 1] = k;
#pragma unroll
                for (int q = KTOP - 1; q > 0; q--) {
                    if (bv[q] > bv[q - 1]) {
                        float tv = bv[q]; bv[q] = bv[q - 1]; bv[q - 1] = tv;
                        int   tk = bk[q]; bk[q] = bk[q - 1]; bk[q - 1] = tk;
                    }
                }
            }
        }

        int series = b * ND + 2 * dp + w;
        for (int r = 0; r < KTOP; r++) {
            float v = bv[0];
            int bestl = lane;
#pragma unroll
            for (int off = 16; off; off >>= 1) {
                float ov = __shfl_xor_sync(0xffffffffu, v, off);
                int   ol = __shfl_xor_sync(0xffffffffu, bestl, off);
                if (ov > v || (ov == v && ol < bestl)) { v = ov; bestl = ol; }
            }
            if (lane == bestl) {
                int k  = bk[0];
                int p1 = (int)(__brev((unsigned)k) >> 21);
                int p2 = (int)(__brev((unsigned)(2048 - k)) >> 21);
                float2 z1 = X[p1];
                float2 z2 = X[p2];
                float A, B;
                if (w == 0) { A = (z1.x + z2.x) * (1.0f / 2048.0f); B = (z1.y - z2.y) * (1.0f / 2048.0f); }
                else        { A = (z1.y + z2.y) * (1.0f / 2048.0f); B = (z2.x - z1.x) * (1.0f / 2048.0f); }
                float tc = 2.0f * g_rot[k].x;                  // 2*cos(2*pi*k/2048)
                g_comps[series * KTOP + r] = make_float4((float)k, A, B, tc);
#pragma unroll
                for (int q = 0; q < KTOP - 1; q++) { bv[q] = bv[q + 1]; bk[q] = bk[q + 1]; }
                bv[KTOP - 1] = -1.0f;
            }
        }
    }
}

// ---------------------------------------------------------------------------
// Kernel C: synthesis via Chebyshev recurrence c_{n+1} = 2cos(w)*c_n - c_{n-1},
// seeded exactly from the 2048-period table per 32-step chunk.
// out[b,tt,d] = sum_j (A_j cos(w_j tt) - B_j sin(w_j tt))
// ---------------------------------------------------------------------------
__global__ void k_synth(float* __restrict__ out) {
    __shared__ float4 sp[ND * KTOP];   // 8 KB
    __shared__ float2 srot[2048];      // 16 KB
    int tid = threadIdx.x;
    int b   = blockIdx.y;

    for (int i = tid; i < ND * KTOP; i += 256)
        sp[i] = g_comps[b * ND * KTOP + i];
    for (int i = tid; i < 2048; i += 256)
        srot[i] = g_rot[i];
    __syncthreads();

    int d   = tid & 63;
    int tt0 = blockIdx.x * 128 + (tid >> 6) * 32;
    if (tt0 >= OUT_T) return;                    // only in last grid.x slice

    float c0[KTOP], c1[KTOP], tc[KTOP];
#pragma unroll
    for (int j = 0; j < KTOP; j++) {
        float4 cc = sp[d * KTOP + j];
        int k = (int)cc.x;
        tc[j] = cc.w;
        float2 r1 = srot[(k * tt0) & 2047];
        float2 r0 = srot[(k * (tt0 - 1)) & 2047];
        c1[j] = cc.y * r1.x - cc.z * r1.y;       // value at tt0
        c0[j] = cc.y * r0.x - cc.z * r0.y;       // value at tt0-1
    }

    float* op = out + ((size_t)b * OUT_T + tt0) * ND + d;
#pragma unroll
    for (int c = 0; c < 32; c += 2) {
        float s1 = ((c1[0] + c1[1]) + (c1[2] + c1[3])) +
                   ((c1[4] + c1[5]) + (c1[6] + c1[7]));
        op[(size_t)c * ND] = s1;
#pragma unroll
        for (int j = 0; j < KTOP; j++) c0[j] = fmaf(tc[j], c1[j], -c0[j]);
        float s2 = ((c0[0] + c0[1]) + (c0[2] + c0[3])) +
                   ((c0[4] + c0[5]) + (c0[6] + c0[7]));
        op[(size_t)(c + 1) * ND] = s2;
#pragma unroll
        for (int j = 0; j < KTOP; j++) c1[j] = fmaf(tc[j], c0[j], -c1[j]);
    }
}

// ---------------------------------------------------------------------------
extern "C" void kernel_launch(void* const* d_in, const int* in_sizes, int n_in,
                              void* d_out, int out_size) {
    const float* x = (const float*)d_in[0];
    float* out = (float*)d_out;

    k_transpose<<<dim3(32, 32), 256>>>(x);
    k_fft_topk<<<NB * ND / 2, 256>>>();
    k_synth<<<dim3(17, NB), 256>>>(out);
}

// round 3
// speedup vs baseline: 1.4303x; 1.2255x over previous
#include <cuda_runtime.h>
#include <math.h>

#define NT     2048
#define NB     32
#define ND     64
#define OUT_T  2144
#define KTOP   8

// Padded smem index: +1 float2 per 8 -> kills 16-way superstage conflicts
#define XP(i) ((i) + ((i) >> 3))

// Scratch (allocation-free: __device__ globals)
__device__ float  g_xt[NB * ND * NT];          // transposed input (b,d,t), 16 MB
__device__ float4 g_comps[NB * ND * KTOP];     // per-series {k, A, B, 2cos(w)}
__device__ float2 g_rot[2048];                 // e^{+2*pi*i*j/2048}

// ---------------------------------------------------------------------------
// Kernel A: transpose (b,t,d) -> (b,d,t), 64x64 tiles, float4 both directions.
// Block (0,0) builds the rotation table with fp32 sincospif (fast, ~1ulp).
// ---------------------------------------------------------------------------
__global__ void k_transpose(const float* __restrict__ x) {
    __shared__ float tile[64][65];
    int b  = blockIdx.y;
    int t0 = blockIdx.x << 6;
    int tid = threadIdx.x;
    int tx = tid & 15;          // float4 column within row
    int ty = tid >> 4;          // 0..15

    const float4* src = (const float4*)(x + ((size_t)b * NT + t0) * ND);
#pragma unroll
    for (int i = 0; i < 4; i++) {
        int r = ty + (i << 4);                 // t within tile
        float4 v = src[r * 16 + tx];
        tile[r][tx * 4 + 0] = v.x;
        tile[r][tx * 4 + 1] = v.y;
        tile[r][tx * 4 + 2] = v.z;
        tile[r][tx * 4 + 3] = v.w;
    }
    __syncthreads();
#pragma unroll
    for (int i = 0; i < 4; i++) {
        int d = ty + (i << 4);                 // full d dimension (ND=64)
        int c = tx * 4;                        // t within tile
        float4 v = make_float4(tile[c][d], tile[c + 1][d], tile[c + 2][d], tile[c + 3][d]);
        *(float4*)(g_xt + ((size_t)(b * ND + d)) * NT + t0 + c) = v;
    }

    if (blockIdx.x == 0 && blockIdx.y == 0) {
#pragma unroll
        for (int j = tid; j < 2048; j += 256) {
            float s, c;
            sincospif((float)j * (1.0f / 1024.0f), &s, &c);   // exact fp32 arg
            g_rot[j] = make_float2(c, s);
        }
    }
}

// ---------------------------------------------------------------------------
// Kernel B: packed-real-pair 2048-pt FFT (fused radix-4 passes + radix-8 tail)
// One block = two real series (d even/odd packed as complex). Output is
// bit-reversed (identical placement to the radix-2 DIF sequence). Smem padded.
// Warp 0/1 then do Hermitian unpack + top-8 for the even/odd series.
// ---------------------------------------------------------------------------
__device__ __forceinline__ float2 cadd(float2 a, float2 b) { return make_float2(a.x + b.x, a.y + b.y); }
__device__ __forceinline__ float2 csub(float2 a, float2 b) { return make_float2(a.x - b.x, a.y - b.y); }
__device__ __forceinline__ float2 cmul(float2 a, float2 b) {
    return make_float2(a.x * b.x - a.y * b.y, a.x * b.y + a.y * b.x);
}

__global__ void k_fft_topk() {
    __shared__ float2 X[NT + (NT >> 3)];   // 18 KB, padded
    __shared__ float2 W[512];              //  4 KB, W[m] = e^{-2*pi*i*m/2048}
    int tid  = threadIdx.x;
    int p    = blockIdx.x;          // pair index: b*32 + dp
    int b    = p >> 5;
    int dp   = p & 31;

    const float4* se = (const float4*)(g_xt + ((size_t)(b * ND + 2 * dp))     * NT);
    const float4* so = (const float4*)(g_xt + ((size_t)(b * ND + 2 * dp + 1)) * NT);
#pragma unroll
    for (int i = 0; i < 2; i++) {
        int idx = tid + (i << 8);              // 0..511 (float4 granularity)
        float4 e = se[idx];
        float4 o = so[idx];
        X[XP(4 * idx + 0)] = make_float2(e.x, o.x);
        X[XP(4 * idx + 1)] = make_float2(e.y, o.y);
        X[XP(4 * idx + 2)] = make_float2(e.z, o.z);
        X[XP(4 * idx + 3)] = make_float2(e.w, o.w);
    }
    for (int j = tid; j < 512; j += 256) {
        float2 r = g_rot[j];
        W[j] = make_float2(r.x, -r.y);
    }
    __syncthreads();

    // Fused radix-4 stages: lh = first-stage hb of each pair -> (10,9),(8,7),(6,5),(4,3)
#pragma unroll
    for (int lh = 10; lh >= 4; lh -= 2) {
        int hh = 1 << (lh - 1);                // quarter stride
#pragma unroll
        for (int it = 0; it < 2; it++) {
            int bi = tid + (it << 8);          // butterfly id 0..511
            int j  = bi & (hh - 1);
            int i0 = ((bi >> (lh - 1)) << (lh + 1)) | j;
            float2 w1 = W[j << (10 - lh)];
            float2 w2 = make_float2(w1.x * w1.x - w1.y * w1.y, 2.0f * w1.x * w1.y);
            float2 wm = make_float2(w1.y, -w1.x);              // -i * w1
            float2 a = X[XP(i0)], bb = X[XP(i0 + hh)], c = X[XP(i0 + 2 * hh)], d = X[XP(i0 + 3 * hh)];
            float2 s0 = cadd(a, c);
            float2 s2 = cmul(csub(a, c), w1);
            float2 s1 = cadd(bb, d);
            float2 s3 = cmul(csub(bb, d), wm);
            X[XP(i0)]          = cadd(s0, s1);
            X[XP(i0 + hh)]     = cmul(csub(s0, s1), w2);
            X[XP(i0 + 2 * hh)] = cadd(s2, s3);
            X[XP(i0 + 3 * hh)] = cmul(csub(s2, s3), w2);
        }
        __syncthreads();
    }

    // Superstage: fused radix-4 (hb 2,1) + final radix-2 (hb 0) on 8 consecutive
    // points per thread. Padded addresses: XP(8*tid + j) == 9*tid + j (contiguous).
    {
        int ph = 9 * tid;
        float2 v[8];
#pragma unroll
        for (int q = 0; q < 8; q++) v[q] = X[ph + q];
        float2 w1_1 = W[256];                                  // e^{-i*pi/4}
#pragma unroll
        for (int j = 0; j < 2; j++) {
            float2 w1 = (j == 0) ? make_float2(1.0f, 0.0f) : w1_1;
            float2 w2 = make_float2(w1.x * w1.x - w1.y * w1.y, 2.0f * w1.x * w1.y);
            float2 wm = make_float2(w1.y, -w1.x);
            float2 a = v[j], bb = v[j + 2], c = v[j + 4], d = v[j + 6];
            float2 s0 = cadd(a, c);
            float2 s2 = cmul(csub(a, c), w1);
            float2 s1 = cadd(bb, d);
            float2 s3 = cmul(csub(bb, d), wm);
            v[j]     = cadd(s0, s1);
            v[j + 2] = cmul(csub(s0, s1), w2);
            v[j + 4] = cadd(s2, s3);
            v[j + 6] = cmul(csub(s2, s3), w2);
        }
        // final radix-2 (twiddle = 1) on consecutive pairs
#pragma unroll
        for (int q = 0; q < 4; q++) {
            float2 a = v[2 * q], bb = v[2 * q + 1];
            X[ph + 2 * q]     = make_float2(a.x + bb.x, a.y + bb.y);
            X[ph + 2 * q + 1] = make_float2(a.x - bb.x, a.y - bb.y);
        }
    }
    __syncthreads();

    // Hermitian unpack + top-8. Warp 0 -> even series, warp 1 -> odd series.
    if (tid < 64) {
        int w    = tid >> 5;
        int lane = tid & 31;
        float bv[KTOP];
        int   bk[KTOP];
#pragma unroll
        for (int q = 0; q < KTOP; q++) { bv[q] = -1.0f; bk[q] = 1; }

        for (int it = 0; it < 32; it++) {
            int k = 1 + lane + 32 * it;
            if (k >= 1024) break;
            int p1 = (int)(__brev((unsigned)k) >> 21);
            int p2 = (int)(__brev((unsigned)(2048 - k)) >> 21);
            float2 z1 = X[XP(p1)];
            float2 z2 = X[XP(p2)];
            float mg;
            if (w == 0) {
                float er = z1.x + z2.x, ei = z1.y - z2.y;
                mg = fmaf(er, er, ei * ei);
            } else {
                float orr = z1.y + z2.y, oi = z2.x - z1.x;
                mg = fmaf(orr, orr, oi * oi);
            }
            if (mg > bv[KTOP - 1]) {
                bv[KTOP - 1] = mg; bk[KTOP - 1] = k;
#pragma unroll
                for (int q = KTOP - 1; q > 0; q--) {
                    if (bv[q] > bv[q - 1]) {
                        float tv = bv[q]; bv[q] = bv[q - 1]; bv[q - 1] = tv;
                        int   tk = bk[q]; bk[q] = bk[q - 1]; bk[q - 1] = tk;
                    }
                }
            }
        }

        int series = b * ND + 2 * dp + w;
        for (int r = 0; r < KTOP; r++) {
            float v = bv[0];
            int bestl = lane;
#pragma unroll
            for (int off = 16; off; off >>= 1) {
                float ov = __shfl_xor_sync(0xffffffffu, v, off);
                int   ol = __shfl_xor_sync(0xffffffffu, bestl, off);
                if (ov > v || (ov == v && ol < bestl)) { v = ov; bestl = ol; }
            }
            if (lane == bestl) {
                int k  = bk[0];
                int p1 = (int)(__brev((unsigned)k) >> 21);
                int p2 = (int)(__brev((unsigned)(2048 - k)) >> 21);
                float2 z1 = X[XP(p1)];
                float2 z2 = X[XP(p2)];
                float A, B;
                if (w == 0) { A = (z1.x + z2.x) * (1.0f / 2048.0f); B = (z1.y - z2.y) * (1.0f / 2048.0f); }
                else        { A = (z1.y + z2.y) * (1.0f / 2048.0f); B = (z2.x - z1.x) * (1.0f / 2048.0f); }
                float tc = 2.0f * g_rot[k].x;                  // 2*cos(2*pi*k/2048)
                g_comps[series * KTOP + r] = make_float4((float)k, A, B, tc);
#pragma unroll
                for (int q = 0; q < KTOP - 1; q++) { bv[q] = bv[q + 1]; bk[q] = bk[q + 1]; }
                bv[KTOP - 1] = -1.0f;
            }
        }
    }
}

// ---------------------------------------------------------------------------
// Kernel C: synthesis via Chebyshev recurrence c_{n+1} = 2cos(w)*c_n - c_{n-1},
// seeded exactly from the 2048-period table per 32-step chunk.
// out[b,tt,d] = sum_j (A_j cos(w_j tt) - B_j sin(w_j tt))
// ---------------------------------------------------------------------------
__global__ void k_synth(float* __restrict__ out) {
    __shared__ float4 sp[ND * KTOP];   // 8 KB
    __shared__ float2 srot[2048];      // 16 KB
    int tid = threadIdx.x;
    int b   = blockIdx.y;

    for (int i = tid; i < ND * KTOP; i += 256)
        sp[i] = g_comps[b * ND * KTOP + i];
    for (int i = tid; i < 2048; i += 256)
        srot[i] = g_rot[i];
    __syncthreads();

    int d   = tid & 63;
    int tt0 = blockIdx.x * 128 + (tid >> 6) * 32;
    if (tt0 >= OUT_T) return;                    // only in last grid.x slice

    float c0[KTOP], c1[KTOP], tc[KTOP];
#pragma unroll
    for (int j = 0; j < KTOP; j++) {
        float4 cc = sp[d * KTOP + j];
        int k = (int)cc.x;
        tc[j] = cc.w;
        float2 r1 = srot[(k * tt0) & 2047];
        float2 r0 = srot[(k * (tt0 - 1)) & 2047];
        c1[j] = cc.y * r1.x - cc.z * r1.y;       // value at tt0
        c0[j] = cc.y * r0.x - cc.z * r0.y;       // value at tt0-1
    }

    float* op = out + ((size_t)b * OUT_T + tt0) * ND + d;
#pragma unroll
    for (int c = 0; c < 32; c += 2) {
        float s1 = ((c1[0] + c1[1]) + (c1[2] + c1[3])) +
                   ((c1[4] + c1[5]) + (c1[6] + c1[7]));
        op[(size_t)c * ND] = s1;
#pragma unroll
        for (int j = 0; j < KTOP; j++) c0[j] = fmaf(tc[j], c1[j], -c0[j]);
        float s2 = ((c0[0] + c0[1]) + (c0[2] + c0[3])) +
                   ((c0[4] + c0[5]) + (c0[6] + c0[7]));
        op[(size_t)(c + 1) * ND] = s2;
#pragma unroll
        for (int j = 0; j < KTOP; j++) c1[j] = fmaf(tc[j], c0[j], -c1[j]);
    }
}

// ---------------------------------------------------------------------------
extern "C" void kernel_launch(void* const* d_in, const int* in_sizes, int n_in,
                              void* d_out, int out_size) {
    const float* x = (const float*)d_in[0];
    float* out = (float*)d_out;

    k_transpose<<<dim3(32, 32), 256>>>(x);
    k_fft_topk<<<NB * ND / 2, 256>>>();
    k_synth<<<dim3(17, NB), 256>>>(out);
}

// round 4
// speedup vs baseline: 1.5158x; 1.0598x over previous
#include <cuda_runtime.h>
#include <math.h>

#define NT     2048
#define NB     32
#define ND     64
#define OUT_T  2144
#define KTOP   8

// Padded smem index: +1 float2 per 8
#define XP(i) ((i) + ((i) >> 3))

// Scratch (allocation-free: __device__ global)
__device__ float4 g_comps[NB * ND * KTOP];     // per-series {k, A, B, 0}

// ---------------------------------------------------------------------------
// Kernel B: packed-real-pair 2048-pt FFT (fused radix-4 passes + radix-8 tail)
// One block = two real series: d = 2dp and 2dp+1, loaded DIRECTLY from the
// (b,t,d) layout — adjacent d means one float2 load gives the complex packing.
// Output bit-reversed (radix-2 DIF placement). Warps 0/1 do Hermitian unpack
// + top-8 for even/odd series.
// ---------------------------------------------------------------------------
__device__ __forceinline__ float2 cadd(float2 a, float2 b) { return make_float2(a.x + b.x, a.y + b.y); }
__device__ __forceinline__ float2 csub(float2 a, float2 b) { return make_float2(a.x - b.x, a.y - b.y); }
__device__ __forceinline__ float2 cmul(float2 a, float2 b) {
    return make_float2(a.x * b.x - a.y * b.y, a.x * b.y + a.y * b.x);
}

__global__ void __launch_bounds__(256) k_fft_topk(const float* __restrict__ x) {
    __shared__ float2 X[NT + (NT >> 3)];   // 18 KB, padded
    __shared__ float2 W[512];              //  4 KB, W[m] = e^{-2*pi*i*m/2048}
    int tid  = threadIdx.x;
    int p    = blockIdx.x;          // pair index: b*32 + dp
    int b    = p >> 5;
    int dp   = p & 31;

    // Twiddles via fp32 sincospif (exact fp32 args, MUFU-fast)
#pragma unroll
    for (int j = tid; j < 512; j += 256) {
        float s, c;
        sincospif((float)j * (1.0f / 1024.0f), &s, &c);
        W[j] = make_float2(c, -s);
    }

    // Direct load from (b,t,d): element (b,t,2dp..2dp+1) is one float2
    const float2* src2 = (const float2*)x + ((size_t)b << 16) + dp;   // b*2048*32 + dp
#pragma unroll
    for (int i = 0; i < 8; i++) {
        int t = tid + (i << 8);
        float2 v = src2[(size_t)t << 5];       // stride 32 float2 = 64 floats per t
        X[XP(t)] = v;                          // (even series, odd series)
    }
    __syncthreads();

    // Fused radix-4 stages: lh = first-stage hb of each pair -> (10,9),(8,7),(6,5),(4,3)
#pragma unroll
    for (int lh = 10; lh >= 4; lh -= 2) {
        int hh = 1 << (lh - 1);                // quarter stride
#pragma unroll
        for (int it = 0; it < 2; it++) {
            int bi = tid + (it << 8);          // butterfly id 0..511
            int j  = bi & (hh - 1);
            int i0 = ((bi >> (lh - 1)) << (lh + 1)) | j;
            float2 w1 = W[j << (10 - lh)];
            float2 w2 = make_float2(w1.x * w1.x - w1.y * w1.y, 2.0f * w1.x * w1.y);
            float2 wm = make_float2(w1.y, -w1.x);              // -i * w1
            float2 a = X[XP(i0)], bb = X[XP(i0 + hh)], c = X[XP(i0 + 2 * hh)], d = X[XP(i0 + 3 * hh)];
            float2 s0 = cadd(a, c);
            float2 s2 = cmul(csub(a, c), w1);
            float2 s1 = cadd(bb, d);
            float2 s3 = cmul(csub(bb, d), wm);
            X[XP(i0)]          = cadd(s0, s1);
            X[XP(i0 + hh)]     = cmul(csub(s0, s1), w2);
            X[XP(i0 + 2 * hh)] = cadd(s2, s3);
            X[XP(i0 + 3 * hh)] = cmul(csub(s2, s3), w2);
        }
        __syncthreads();
    }

    // Superstage: fused radix-4 (hb 2,1) + final radix-2 (hb 0) on 8 consecutive
    // points per thread. Padded addresses: XP(8*tid + j) == 9*tid + j.
    {
        int ph = 9 * tid;
        float2 v[8];
#pragma unroll
        for (int q = 0; q < 8; q++) v[q] = X[ph + q];
        float2 w1_1 = W[256];                                  // e^{-i*pi/4}
#pragma unroll
        for (int j = 0; j < 2; j++) {
            float2 w1 = (j == 0) ? make_float2(1.0f, 0.0f) : w1_1;
            float2 w2 = make_float2(w1.x * w1.x - w1.y * w1.y, 2.0f * w1.x * w1.y);
            float2 wm = make_float2(w1.y, -w1.x);
            float2 a = v[j], bb = v[j + 2], c = v[j + 4], d = v[j + 6];
            float2 s0 = cadd(a, c);
            float2 s2 = cmul(csub(a, c), w1);
            float2 s1 = cadd(bb, d);
            float2 s3 = cmul(csub(bb, d), wm);
            v[j]     = cadd(s0, s1);
            v[j + 2] = cmul(csub(s0, s1), w2);
            v[j + 4] = cadd(s2, s3);
            v[j + 6] = cmul(csub(s2, s3), w2);
        }
#pragma unroll
        for (int q = 0; q < 4; q++) {
            float2 a = v[2 * q], bb = v[2 * q + 1];
            X[ph + 2 * q]     = make_float2(a.x + bb.x, a.y + bb.y);
            X[ph + 2 * q + 1] = make_float2(a.x - bb.x, a.y - bb.y);
        }
    }
    __syncthreads();

    // Hermitian unpack + top-8. Warp 0 -> even series, warp 1 -> odd series.
    if (tid < 64) {
        int w    = tid >> 5;
        int lane = tid & 31;
        float bv[KTOP];
        int   bk[KTOP];
#pragma unroll
        for (int q = 0; q < KTOP; q++) { bv[q] = -1.0f; bk[q] = 1; }

        for (int it = 0; it < 32; it++) {
            int k = 1 + lane + 32 * it;
            if (k >= 1024) break;
            int p1 = (int)(__brev((unsigned)k) >> 21);
            int p2 = (int)(__brev((unsigned)(2048 - k)) >> 21);
            float2 z1 = X[XP(p1)];
            float2 z2 = X[XP(p2)];
            float mg;
            if (w == 0) {
                float er = z1.x + z2.x, ei = z1.y - z2.y;
                mg = fmaf(er, er, ei * ei);
            } else {
                float orr = z1.y + z2.y, oi = z2.x - z1.x;
                mg = fmaf(orr, orr, oi * oi);
            }
            if (mg > bv[KTOP - 1]) {
                bv[KTOP - 1] = mg; bk[KTOP - 1] = k;
#pragma unroll
                for (int q = KTOP - 1; q > 0; q--) {
                    if (bv[q] > bv[q - 1]) {
                        float tv = bv[q]; bv[q] = bv[q - 1]; bv[q - 1] = tv;
                        int   tk = bk[q]; bk[q] = bk[q - 1]; bk[q - 1] = tk;
                    }
                }
            }
        }

        int series = b * ND + 2 * dp + w;
        for (int r = 0; r < KTOP; r++) {
            float v = bv[0];
            int bestl = lane;
#pragma unroll
            for (int off = 16; off; off >>= 1) {
                float ov = __shfl_xor_sync(0xffffffffu, v, off);
                int   ol = __shfl_xor_sync(0xffffffffu, bestl, off);
                if (ov > v || (ov == v && ol < bestl)) { v = ov; bestl = ol; }
            }
            if (lane == bestl) {
                int k  = bk[0];
                int p1 = (int)(__brev((unsigned)k) >> 21);
                int p2 = (int)(__brev((unsigned)(2048 - k)) >> 21);
                float2 z1 = X[XP(p1)];
                float2 z2 = X[XP(p2)];
                float A, B;
                if (w == 0) { A = (z1.x + z2.x) * (1.0f / 2048.0f); B = (z1.y - z2.y) * (1.0f / 2048.0f); }
                else        { A = (z1.y + z2.y) * (1.0f / 2048.0f); B = (z2.x - z1.x) * (1.0f / 2048.0f); }
                g_comps[series * KTOP + r] = make_float4((float)k, A, B, 0.0f);
#pragma unroll
                for (int q = 0; q < KTOP - 1; q++) { bv[q] = bv[q + 1]; bk[q] = bk[q + 1]; }
                bv[KTOP - 1] = -1.0f;
            }
        }
    }
}

// ---------------------------------------------------------------------------
// Kernel C: synthesis via Chebyshev recurrence c_{n+1} = 2cos(w)*c_n - c_{n-1},
// seeded exactly per 32-step chunk with sincospif (period-2048 exact args).
// No shared memory. Each thread: 2 adjacent d, 32 time steps, float2 stores.
// out[b,tt,d] = sum_j (A_j cos(w_j tt) - B_j sin(w_j tt))
// ---------------------------------------------------------------------------
__global__ void __launch_bounds__(256) k_synth(float* __restrict__ out) {
    int tid = threadIdx.x;
    int b   = blockIdx.y;
    int dp  = tid & 31;                        // d pair: d = 2dp, 2dp+1
    int tt0 = blockIdx.x * 256 + (tid >> 5) * 32;
    if (tt0 >= OUT_T) return;

    float c0[2 * KTOP], c1[2 * KTOP], tc[2 * KTOP];
#pragma unroll
    for (int e = 0; e < 2; e++) {
        const float4* cp = g_comps + ((size_t)(b * ND + 2 * dp + e)) * KTOP;
#pragma unroll
        for (int j = 0; j < KTOP; j++) {
            float4 cc = cp[j];
            int k = (int)cc.x;
            float sw, cw;
            sincospif((float)k * (1.0f / 1024.0f), &sw, &cw);
            float s1, co1;
            sincospif((float)((k * tt0) & 2047) * (1.0f / 1024.0f), &s1, &co1);
            int q = e * KTOP + j;
            tc[q] = 2.0f * cw;
            c1[q] = cc.y * co1 - cc.z * s1;                    // value at tt0
            // back-rotate one step: cos(th-w), sin(th-w)
            float cm = co1 * cw + s1 * sw;
            float sm = s1 * cw - co1 * sw;
            c0[q] = cc.y * cm - cc.z * sm;                     // value at tt0-1
        }
    }

    float2* op = (float2*)(out + ((size_t)b * OUT_T + tt0) * ND) + dp;
#pragma unroll
    for (int c = 0; c < 32; c += 2) {
        float sa1 = ((c1[0] + c1[1]) + (c1[2] + c1[3])) + ((c1[4] + c1[5]) + (c1[6] + c1[7]));
        float sb1 = ((c1[8] + c1[9]) + (c1[10] + c1[11])) + ((c1[12] + c1[13]) + (c1[14] + c1[15]));
        op[(size_t)c * 32] = make_float2(sa1, sb1);
#pragma unroll
        for (int q = 0; q < 2 * KTOP; q++) c0[q] = fmaf(tc[q], c1[q], -c0[q]);
        float sa2 = ((c0[0] + c0[1]) + (c0[2] + c0[3])) + ((c0[4] + c0[5]) + (c0[6] + c0[7]));
        float sb2 = ((c0[8] + c0[9]) + (c0[10] + c0[11])) + ((c0[12] + c0[13]) + (c0[14] + c0[15]));
        op[(size_t)(c + 1) * 32] = make_float2(sa2, sb2);
#pragma unroll
        for (int q = 0; q < 2 * KTOP; q++) c1[q] = fmaf(tc[q], c0[q], -c1[q]);
    }
}

// ---------------------------------------------------------------------------
extern "C" void kernel_launch(void* const* d_in, const int* in_sizes, int n_in,
                              void* d_out, int out_size) {
    const float* x = (const float*)d_in[0];
    float* out = (float*)d_out;

    k_fft_topk<<<NB * ND / 2, 256>>>(x);
    k_synth<<<dim3(9, NB), 256>>>(out);
}

// round 5
// speedup vs baseline: 1.7095x; 1.1278x over previous
#include <cuda_runtime.h>
#include <math.h>

#define NT     2048
#define NB     32
#define ND     64
#define OUT_T  2144
#define KTOP   8

// Padded smem index: +1 float2 per 8
#define XP(i) ((i) + ((i) >> 3))

// Scratch (allocation-free: __device__ global)
__device__ float4 g_comps[NB * ND * KTOP];     // per-series {k, A, B, 0}

__device__ __forceinline__ float2 cadd(float2 a, float2 b) { return make_float2(a.x + b.x, a.y + b.y); }
__device__ __forceinline__ float2 csub(float2 a, float2 b) { return make_float2(a.x - b.x, a.y - b.y); }
__device__ __forceinline__ float2 cmul(float2 a, float2 b) {
    return make_float2(a.x * b.x - a.y * b.y, a.x * b.y + a.y * b.x);
}

// ---------------------------------------------------------------------------
// Kernel B: TWO packed-real-pair 2048-pt FFTs per block (4 series = one float4
// column of the (b,t,d) input). Fused radix-4 passes + radix-8 register tail.
// Per-stage compact twiddle tables (conflict-free LDS). Warps 0-3 do Hermitian
// unpack + top-8, one warp per series.
// ---------------------------------------------------------------------------
__global__ void __launch_bounds__(256) k_fft_topk(const float* __restrict__ x) {
    __shared__ float2 X0[NT + (NT >> 3)];   // 18 KB
    __shared__ float2 X1[NT + (NT >> 3)];   // 18 KB
    __shared__ float2 W10[512];             // stage hh=512 twiddles
    __shared__ float2 W8[128];              // stage hh=128
    __shared__ float2 W6[32];               // stage hh=32
    __shared__ float2 W4[8];                // stage hh=8
    int tid = threadIdx.x;
    int b   = blockIdx.x >> 4;
    int dq  = blockIdx.x & 15;              // float4 column: d = 4dq..4dq+3

    // Per-stage twiddle tables, W*[j] = e^{-2*pi*i * j * (2048/ (4*hh)) /2048}
    {
        float s, c;
        sincospif((float)tid * (1.0f / 1024.0f), &s, &c);
        W10[tid] = make_float2(c, -s);
        sincospif((float)(tid + 256) * (1.0f / 1024.0f), &s, &c);
        W10[tid + 256] = make_float2(c, -s);
        if (tid < 128) { sincospif((float)tid * (1.0f / 256.0f), &s, &c); W8[tid] = make_float2(c, -s); }
        if (tid < 32)  { sincospif((float)tid * (1.0f / 64.0f),  &s, &c); W6[tid] = make_float2(c, -s); }
        if (tid < 8)   { sincospif((float)tid * (1.0f / 16.0f),  &s, &c); W4[tid] = make_float2(c, -s); }
    }

    // Direct float4 load from (b,t,d): (d0,d1) -> X0, (d2,d3) -> X1
    const float4* src4 = (const float4*)x + ((size_t)b * NT) * 16 + dq;
#pragma unroll
    for (int i = 0; i < 8; i++) {
        int t = tid + (i << 8);
        float4 v = src4[(size_t)t * 16];
        X0[XP(t)] = make_float2(v.x, v.y);
        X1[XP(t)] = make_float2(v.z, v.w);
    }
    __syncthreads();

    // Fused radix-4 stages over both arrays: lh = 10,8,6,4
#pragma unroll
    for (int lh = 10; lh >= 4; lh -= 2) {
        int hh = 1 << (lh - 1);                // quarter stride
        const float2* Wt = (lh == 10) ? W10 : (lh == 8) ? W8 : (lh == 6) ? W6 : W4;
#pragma unroll
        for (int it = 0; it < 4; it++) {
            float2* A = (it < 2) ? X0 : X1;
            int bi = tid + ((it & 1) << 8);    // butterfly id 0..511
            int j  = bi & (hh - 1);
            int i0 = ((bi >> (lh - 1)) << (lh + 1)) | j;
            float2 w1 = Wt[j];
            float2 w2 = make_float2(w1.x * w1.x - w1.y * w1.y, 2.0f * w1.x * w1.y);
            float2 wm = make_float2(w1.y, -w1.x);              // -i * w1
            float2 a = A[XP(i0)], bb = A[XP(i0 + hh)], c = A[XP(i0 + 2 * hh)], d = A[XP(i0 + 3 * hh)];
            float2 s0 = cadd(a, c);
            float2 s2 = cmul(csub(a, c), w1);
            float2 s1 = cadd(bb, d);
            float2 s3 = cmul(csub(bb, d), wm);
            A[XP(i0)]          = cadd(s0, s1);
            A[XP(i0 + hh)]     = cmul(csub(s0, s1), w2);
            A[XP(i0 + 2 * hh)] = cadd(s2, s3);
            A[XP(i0 + 3 * hh)] = cmul(csub(s2, s3), w2);
        }
        __syncthreads();
    }

    // Superstage: fused radix-4 (hb 2,1) + final radix-2 (hb 0) on 8 consecutive
    // points per thread, per array. XP(8*tid + q) == 9*tid + q.
#pragma unroll
    for (int arr = 0; arr < 2; arr++) {
        float2* A = arr ? X1 : X0;
        int ph = 9 * tid;
        float2 v[8];
#pragma unroll
        for (int q = 0; q < 8; q++) v[q] = A[ph + q];
#pragma unroll
        for (int j = 0; j < 2; j++) {
            float2 w1 = (j == 0) ? make_float2(1.0f, 0.0f)
                                 : make_float2(0.70710678118654752f, -0.70710678118654752f);
            float2 w2 = make_float2(w1.x * w1.x - w1.y * w1.y, 2.0f * w1.x * w1.y);
            float2 wm = make_float2(w1.y, -w1.x);
            float2 a = v[j], bb = v[j + 2], c = v[j + 4], d = v[j + 6];
            float2 s0 = cadd(a, c);
            float2 s2 = cmul(csub(a, c), w1);
            float2 s1 = cadd(bb, d);
            float2 s3 = cmul(csub(bb, d), wm);
            v[j]     = cadd(s0, s1);
            v[j + 2] = cmul(csub(s0, s1), w2);
            v[j + 4] = cadd(s2, s3);
            v[j + 6] = cmul(csub(s2, s3), w2);
        }
#pragma unroll
        for (int q = 0; q < 4; q++) {
            float2 a = v[2 * q], bb = v[2 * q + 1];
            A[ph + 2 * q]     = make_float2(a.x + bb.x, a.y + bb.y);
            A[ph + 2 * q + 1] = make_float2(a.x - bb.x, a.y - bb.y);
        }
    }
    __syncthreads();

    // Hermitian unpack + top-8: warp w handles series d = 4dq + w.
    if (tid < 128) {
        int w    = tid >> 5;
        int lane = tid & 31;
        const float2* A = (w < 2) ? X0 : X1;
        int odd = w & 1;
        float bv[KTOP];
        int   bk[KTOP];
#pragma unroll
        for (int q = 0; q < KTOP; q++) { bv[q] = -1.0f; bk[q] = 1; }

        for (int it = 0; it < 32; it++) {
            int k = 1 + lane + 32 * it;
            if (k >= 1024) break;
            int p1 = (int)(__brev((unsigned)k) >> 21);
            int p2 = (int)(__brev((unsigned)(2048 - k)) >> 21);
            float2 z1 = A[XP(p1)];
            float2 z2 = A[XP(p2)];
            float mg;
            if (odd == 0) {
                float er = z1.x + z2.x, ei = z1.y - z2.y;
                mg = fmaf(er, er, ei * ei);
            } else {
                float orr = z1.y + z2.y, oi = z2.x - z1.x;
                mg = fmaf(orr, orr, oi * oi);
            }
            if (mg > bv[KTOP - 1]) {
                bv[KTOP - 1] = mg; bk[KTOP - 1] = k;
#pragma unroll
                for (int q = KTOP - 1; q > 0; q--) {
                    if (bv[q] > bv[q - 1]) {
                        float tv = bv[q]; bv[q] = bv[q - 1]; bv[q - 1] = tv;
                        int   tk = bk[q]; bk[q] = bk[q - 1]; bk[q - 1] = tk;
                    }
                }
            }
        }

        int series = b * ND + 4 * dq + w;
        for (int r = 0; r < KTOP; r++) {
            float v = bv[0];
            int bestl = lane;
#pragma unroll
            for (int off = 16; off; off >>= 1) {
                float ov = __shfl_xor_sync(0xffffffffu, v, off);
                int   ol = __shfl_xor_sync(0xffffffffu, bestl, off);
                if (ov > v || (ov == v && ol < bestl)) { v = ov; bestl = ol; }
            }
            if (lane == bestl) {
                int k  = bk[0];
                int p1 = (int)(__brev((unsigned)k) >> 21);
                int p2 = (int)(__brev((unsigned)(2048 - k)) >> 21);
                float2 z1 = A[XP(p1)];
                float2 z2 = A[XP(p2)];
                float Aa, Bb;
                if (odd == 0) { Aa = (z1.x + z2.x) * (1.0f / 2048.0f); Bb = (z1.y - z2.y) * (1.0f / 2048.0f); }
                else          { Aa = (z1.y + z2.y) * (1.0f / 2048.0f); Bb = (z2.x - z1.x) * (1.0f / 2048.0f); }
                g_comps[series * KTOP + r] = make_float4((float)k, Aa, Bb, 0.0f);
#pragma unroll
                for (int q = 0; q < KTOP - 1; q++) { bv[q] = bv[q + 1]; bk[q] = bk[q + 1]; }
                bv[KTOP - 1] = -1.0f;
            }
        }
    }
}

// ---------------------------------------------------------------------------
// Kernel C: Chebyshev-recurrence synthesis, 1 d per thread, 8 harmonics,
// seeded per 32-step chunk with sincospif (period-2048 exact args).
// ---------------------------------------------------------------------------
__global__ void __launch_bounds__(256) k_synth(float* __restrict__ out) {
    int tid = threadIdx.x;
    int b   = blockIdx.y;
    int d   = tid & 63;
    int tt0 = (blockIdx.x * 4 + (tid >> 6)) * 32;
    if (tt0 >= OUT_T) return;

    const float4* cp = g_comps + ((size_t)(b * ND + d)) * KTOP;
    float c0[KTOP], c1[KTOP], tc[KTOP];
#pragma unroll
    for (int j = 0; j < KTOP; j++) {
        float4 cc = cp[j];
        int k = (int)cc.x;
        float sw, cw;
        sincospif((float)k * (1.0f / 1024.0f), &sw, &cw);
        float s1, co1;
        sincospif((float)((k * tt0) & 2047) * (1.0f / 1024.0f), &s1, &co1);
        tc[j] = 2.0f * cw;
        c1[j] = cc.y * co1 - cc.z * s1;                    // value at tt0
        float cm = co1 * cw + s1 * sw;                     // cos(th - w)
        float sm = s1 * cw - co1 * sw;                     // sin(th - w)
        c0[j] = cc.y * cm - cc.z * sm;                     // value at tt0-1
    }

    float* op = out + ((size_t)b * OUT_T + tt0) * ND + d;
#pragma unroll
    for (int c = 0; c < 32; c += 2) {
        float s1 = ((c1[0] + c1[1]) + (c1[2] + c1[3])) + ((c1[4] + c1[5]) + (c1[6] + c1[7]));
        op[(size_t)c * ND] = s1;
#pragma unroll
        for (int j = 0; j < KTOP; j++) c0[j] = fmaf(tc[j], c1[j], -c0[j]);
        float s2 = ((c0[0] + c0[1]) + (c0[2] + c0[3])) + ((c0[4] + c0[5]) + (c0[6] + c0[7]));
        op[(size_t)(c + 1) * ND] = s2;
#pragma unroll
        for (int j = 0; j < KTOP; j++) c1[j] = fmaf(tc[j], c0[j], -c1[j]);
    }
}

// Nop kernel: shifts the ncu capture window (launch #10) onto k_fft_topk.
__global__ void k_nop() {}

// ---------------------------------------------------------------------------
extern "C" void kernel_launch(void* const* d_in, const int* in_sizes, int n_in,
                              void* d_out, int out_size) {
    const float* x = (const float*)d_in[0];
    float* out = (float*)d_out;

    k_fft_topk<<<NB * 16, 256>>>(x);
    k_synth<<<dim3(17, NB), 256>>>(out);
    k_nop<<<1, 32>>>();
}

// round 6
// speedup vs baseline: 2.0991x; 1.2279x over previous
#include <cuda_runtime.h>
#include <math.h>

#define NT     2048
#define NB     32
#define ND     64
#define OUT_T  2144
#define KTOP   8

// Padding: +1 float2 per 32 -> unit-stride stays conflict-free, strided <=2-way
#define P(i) ((i) + ((i) >> 5))

// Scratch (allocation-free: __device__ global)
__device__ float4 g_comps[NB * ND * KTOP];     // per-series {k, A, B, 0}

__device__ __forceinline__ float2 cadd(float2 a, float2 b) { return make_float2(a.x + b.x, a.y + b.y); }
__device__ __forceinline__ float2 csub(float2 a, float2 b) { return make_float2(a.x - b.x, a.y - b.y); }
__device__ __forceinline__ float2 cmul(float2 a, float2 b) {
    return make_float2(a.x * b.x - a.y * b.y, a.x * b.y + a.y * b.x);
}

// y_r = sum_m a_m * w8^{m r},  w8 = e^{-i pi/4}
__device__ __forceinline__ void dft8(const float2* a, float2* y) {
    float2 z0 = cadd(a[0], a[4]), z1 = csub(a[0], a[4]);
    float2 z2 = cadd(a[2], a[6]), z3 = csub(a[2], a[6]);
    float2 E0 = cadd(z0, z2), E2 = csub(z0, z2);
    float2 E1 = make_float2(z1.x + z3.y, z1.y - z3.x);   // z1 - i z3
    float2 E3 = make_float2(z1.x - z3.y, z1.y + z3.x);   // z1 + i z3
    float2 u0 = cadd(a[1], a[5]), u1 = csub(a[1], a[5]);
    float2 u2 = cadd(a[3], a[7]), u3 = csub(a[3], a[7]);
    float2 O0 = cadd(u0, u2), O2 = csub(u0, u2);
    float2 O1 = make_float2(u1.x + u3.y, u1.y - u3.x);
    float2 O3 = make_float2(u1.x - u3.y, u1.y + u3.x);
    const float s = 0.70710678118654752f;
    float2 T1 = make_float2(s * (O1.x + O1.y), s * (O1.y - O1.x));   // O1 * w8
    float2 T2 = make_float2(O2.y, -O2.x);                            // O2 * w8^2
    float2 T3 = make_float2(s * (O3.y - O3.x), -s * (O3.x + O3.y));  // O3 * w8^3
    y[0] = cadd(E0, O0); y[4] = csub(E0, O0);
    y[1] = cadd(E1, T1); y[5] = csub(E1, T1);
    y[2] = cadd(E2, T2); y[6] = csub(E2, T2);
    y[3] = cadd(E3, T3); y[7] = csub(E3, T3);
}

// Output position of frequency k (mixed-radix 8,8,4,8 DIF digit reversal)
__device__ __forceinline__ int posk(int k) {
    return ((k >> 8) & 7) | (((k >> 6) & 3) << 3) | (((k >> 3) & 7) << 5) | ((k & 7) << 8);
}

// ---------------------------------------------------------------------------
// Kernel B: packed-real-pair 2048-pt FFT, register mixed-radix 8*8*4*8.
// One block = two real series (d = 2dp, 2dp+1 packed as complex via one
// float2 load from the native (b,t,d) layout). 7 smem passes total.
// ---------------------------------------------------------------------------
__global__ void __launch_bounds__(256) k_fft_topk(const float* __restrict__ x) {
    __shared__ float2 X[2112];          // padded 2048
    __shared__ float2 cand[64];         // 2 series x 32 candidates {mag, k}
    int tid = threadIdx.x;
    int b   = blockIdx.x >> 5;
    int dp  = blockIdx.x & 31;
    int lane = tid & 31;

    // ---- Stage 1: radix-8, stride 256, direct from gmem ----
    {
        float2 v[8], y[8];
        const float2* src2 = (const float2*)x + ((size_t)b << 16) + dp;
#pragma unroll
        for (int m = 0; m < 8; m++) v[m] = src2[(size_t)(tid + (m << 8)) << 5];
        dft8(v, y);
        float sw, cw;
        sincospif((float)tid * (1.0f / 1024.0f), &sw, &cw);
        float2 w1 = make_float2(cw, -sw);
        float2 w2 = cmul(w1, w1), w3 = cmul(w2, w1), w4 = cmul(w2, w2);
        float2 w5 = cmul(w3, w2), w6 = cmul(w3, w3), w7 = cmul(w4, w3);
        X[P(tid)]        = y[0];
        X[P(tid + 256)]  = cmul(y[1], w1);
        X[P(tid + 512)]  = cmul(y[2], w2);
        X[P(tid + 768)]  = cmul(y[3], w3);
        X[P(tid + 1024)] = cmul(y[4], w4);
        X[P(tid + 1280)] = cmul(y[5], w5);
        X[P(tid + 1536)] = cmul(y[6], w6);
        X[P(tid + 1792)] = cmul(y[7], w7);
    }
    __syncthreads();

    // ---- Stage 2: radix-8, stride 32, within 256-blocks ----
    {
        int s = tid >> 5, j = lane;
        int base = (s << 8) + j;
        float2 v[8], y[8];
#pragma unroll
        for (int m = 0; m < 8; m++) v[m] = X[P(base + (m << 5))];
        dft8(v, y);
        float sw, cw;
        sincospif((float)j * (1.0f / 128.0f), &sw, &cw);
        float2 w1 = make_float2(cw, -sw);
        float2 w2 = cmul(w1, w1), w3 = cmul(w2, w1), w4 = cmul(w2, w2);
        float2 w5 = cmul(w3, w2), w6 = cmul(w3, w3), w7 = cmul(w4, w3);
        X[P(base)]        = y[0];
        X[P(base + 32)]   = cmul(y[1], w1);
        X[P(base + 64)]   = cmul(y[2], w2);
        X[P(base + 96)]   = cmul(y[3], w3);
        X[P(base + 128)]  = cmul(y[4], w4);
        X[P(base + 160)]  = cmul(y[5], w5);
        X[P(base + 192)]  = cmul(y[6], w6);
        X[P(base + 224)]  = cmul(y[7], w7);
    }
    __syncthreads();

    // ---- Stage 3: radix-4, stride 8, within 32-blocks (2 items/thread) ----
#pragma unroll
    for (int n = 0; n < 2; n++) {
        int e = tid + (n << 8);
        int base = ((e >> 3) << 5) + (e & 7);
        float2 a = X[P(base)], bb = X[P(base + 8)], c = X[P(base + 16)], d = X[P(base + 24)];
        float2 z0 = cadd(a, c), z1 = csub(a, c), z2 = cadd(bb, d), z3 = csub(bb, d);
        float2 y0 = cadd(z0, z2), y2 = csub(z0, z2);
        float2 y1 = make_float2(z1.x + z3.y, z1.y - z3.x);
        float2 y3 = make_float2(z1.x - z3.y, z1.y + z3.x);
        float sw, cw;
        sincospif((float)(e & 7) * (1.0f / 16.0f), &sw, &cw);
        float2 w1 = make_float2(cw, -sw);
        float2 w2 = cmul(w1, w1), w3 = cmul(w2, w1);
        X[P(base)]      = y0;
        X[P(base + 8)]  = cmul(y1, w1);
        X[P(base + 16)] = cmul(y2, w2);
        X[P(base + 24)] = cmul(y3, w3);
    }
    __syncthreads();

    // ---- Stage 4: radix-8 on 8 consecutive points (contiguous after P) ----
    {
        int ph = P(tid << 3);
        float2 v[8], y[8];
#pragma unroll
        for (int q = 0; q < 8; q++) v[q] = X[ph + q];
        dft8(v, y);
#pragma unroll
        for (int q = 0; q < 8; q++) X[ph + q] = y[q];
    }
    __syncthreads();

    // ---- Top-8: 8 warps scan (4 quarters x 2 series), then 2 merge warps ----
    {
        int w       = tid >> 5;
        int odd     = w >> 2;       // series parity: 0 -> d=2dp, 1 -> d=2dp+1
        int quarter = w & 3;
        float bv[KTOP];
        int   bk[KTOP];
#pragma unroll
        for (int q = 0; q < KTOP; q++) { bv[q] = -1.0f; bk[q] = 1; }

#pragma unroll
        for (int it = 0; it < 8; it++) {
            int k = (quarter << 8) + (it << 5) + lane;
            if (k == 0) continue;
            float2 z1 = X[P(posk(k))];
            float2 z2 = X[P(posk(2048 - k))];
            float mg;
            if (odd == 0) {
                float er = z1.x + z2.x, ei = z1.y - z2.y;
                mg = fmaf(er, er, ei * ei);
            } else {
                float orr = z1.y + z2.y, oi = z2.x - z1.x;
                mg = fmaf(orr, orr, oi * oi);
            }
            if (mg > bv[KTOP - 1]) {
                bv[KTOP - 1] = mg; bk[KTOP - 1] = k;
#pragma unroll
                for (int q = KTOP - 1; q > 0; q--) {
                    if (bv[q] > bv[q - 1]) {
                        float tv = bv[q]; bv[q] = bv[q - 1]; bv[q - 1] = tv;
                        int   tk = bk[q]; bk[q] = bk[q - 1]; bk[q - 1] = tk;
                    }
                }
            }
        }

        // warp-level top-8 -> cand[odd*32 + quarter*8 + r]
        for (int r = 0; r < KTOP; r++) {
            float v = bv[0];
            int bestl = lane;
#pragma unroll
            for (int off = 16; off; off >>= 1) {
                float ov = __shfl_xor_sync(0xffffffffu, v, off);
                int   ol = __shfl_xor_sync(0xffffffffu, bestl, off);
                if (ov > v || (ov == v && ol < bestl)) { v = ov; bestl = ol; }
            }
            if (lane == bestl) {
                cand[(odd << 5) + (quarter << 3) + r] = make_float2(bv[0], __int_as_float(bk[0]));
#pragma unroll
                for (int q = 0; q < KTOP - 1; q++) { bv[q] = bv[q + 1]; bk[q] = bk[q + 1]; }
                bv[KTOP - 1] = -1.0f;
            }
        }
    }
    __syncthreads();

    // Merge: warp 0 -> series 0, warp 1 -> series 1 (32 candidates each)
    if (tid < 64) {
        int series = tid >> 5;
        float2 cd = cand[(series << 5) + lane];
        float mv = cd.x;
        int   mk = __float_as_int(cd.y);
        int   kout = 1;
        for (int r = 0; r < KTOP; r++) {
            float v = mv;
            int bestl = lane;
#pragma unroll
            for (int off = 16; off; off >>= 1) {
                float ov = __shfl_xor_sync(0xffffffffu, v, off);
                int   ol = __shfl_xor_sync(0xffffffffu, bestl, off);
                if (ov > v || (ov == v && ol < bestl)) { v = ov; bestl = ol; }
            }
            int wk = __shfl_sync(0xffffffffu, mk, bestl);
            if (lane == bestl) mv = -1.0f;
            if (lane == r) kout = wk;
        }
        if (lane < KTOP) {
            int k = kout;
            float2 z1 = X[P(posk(k))];
            float2 z2 = X[P(posk(2048 - k))];
            float A, B;
            const float inv = 1.0f / 2048.0f;
            if (series == 0) { A = (z1.x + z2.x) * inv; B = (z1.y - z2.y) * inv; }
            else             { A = (z1.y + z2.y) * inv; B = (z2.x - z1.x) * inv; }
            g_comps[((size_t)(b * ND + 2 * dp + series)) * KTOP + lane] =
                make_float4((float)k, A, B, 0.0f);
        }
    }
}

// ---------------------------------------------------------------------------
// Kernel C: Chebyshev-recurrence synthesis, 1 d per thread, 8 harmonics,
// seeded per 32-step chunk with sincospif. 128-thread blocks for occupancy.
// ---------------------------------------------------------------------------
__global__ void __launch_bounds__(128) k_synth(float* __restrict__ out) {
    int tid = threadIdx.x;
    int b   = blockIdx.y;
    int d   = tid & 63;
    int tt0 = (blockIdx.x * 2 + (tid >> 6)) * 32;
    if (tt0 >= OUT_T) return;

    const float4* cp = g_comps + ((size_t)(b * ND + d)) * KTOP;
    float c0[KTOP], c1[KTOP], tc[KTOP];
#pragma unroll
    for (int j = 0; j < KTOP; j++) {
        float4 cc = cp[j];
        int k = (int)cc.x;
        float sw, cw;
        sincospif((float)k * (1.0f / 1024.0f), &sw, &cw);
        float s1, co1;
        sincospif((float)((k * tt0) & 2047) * (1.0f / 1024.0f), &s1, &co1);
        tc[j] = 2.0f * cw;
        c1[j] = cc.y * co1 - cc.z * s1;                    // value at tt0
        float cm = co1 * cw + s1 * sw;                     // cos(th - w)
        float sm = s1 * cw - co1 * sw;                     // sin(th - w)
        c0[j] = cc.y * cm - cc.z * sm;                     // value at tt0-1
    }

    float* op = out + ((size_t)b * OUT_T + tt0) * ND + d;
#pragma unroll
    for (int c = 0; c < 32; c += 2) {
        float s1 = ((c1[0] + c1[1]) + (c1[2] + c1[3])) + ((c1[4] + c1[5]) + (c1[6] + c1[7]));
        op[(size_t)c * ND] = s1;
#pragma unroll
        for (int j = 0; j < KTOP; j++) c0[j] = fmaf(tc[j], c1[j], -c0[j]);
        float s2 = ((c0[0] + c0[1]) + (c0[2] + c0[3])) + ((c0[4] + c0[5]) + (c0[6] + c0[7]));
        op[(size_t)(c + 1) * ND] = s2;
#pragma unroll
        for (int j = 0; j < KTOP; j++) c1[j] = fmaf(tc[j], c0[j], -c1[j]);
    }
}

// Nop kernel: keeps 3 launches/replay so the ncu window stays on k_fft_topk.
__global__ void k_nop() {}

// ---------------------------------------------------------------------------
extern "C" void kernel_launch(void* const* d_in, const int* in_sizes, int n_in,
                              void* d_out, int out_size) {
    const float* x = (const float*)d_in[0];
    float* out = (float*)d_out;

    k_fft_topk<<<NB * 32, 256>>>(x);
    k_synth<<<dim3(34, NB), 128>>>(out);
    k_nop<<<1, 32>>>();
}

// round 7
// speedup vs baseline: 2.4203x; 1.1530x over previous
#include <cuda_runtime.h>
#include <math.h>

#define NT     2048
#define NB     32
#define ND     64
#define OUT_T  2144
#define KTOP   8

// Padding: +1 float2 per 8. Verified <=2-3-way for every access pattern below;
// makes 8-consecutive physically contiguous: XP(8t+q) = 9t+q.
#define XP(i) ((i) + ((i) >> 3))

// Scratch (allocation-free: __device__ global)
__device__ float4 g_comps[NB * ND * KTOP];     // per-series {k, A, B, 0}

__device__ __forceinline__ float2 cadd(float2 a, float2 b) { return make_float2(a.x + b.x, a.y + b.y); }
__device__ __forceinline__ float2 csub(float2 a, float2 b) { return make_float2(a.x - b.x, a.y - b.y); }
__device__ __forceinline__ float2 cmul(float2 a, float2 b) {
    return make_float2(a.x * b.x - a.y * b.y, a.x * b.y + a.y * b.x);
}

// y_r = sum_m a_m * w8^{m r},  w8 = e^{-i pi/4}
__device__ __forceinline__ void dft8(const float2* a, float2* y) {
    float2 z0 = cadd(a[0], a[4]), z1 = csub(a[0], a[4]);
    float2 z2 = cadd(a[2], a[6]), z3 = csub(a[2], a[6]);
    float2 E0 = cadd(z0, z2), E2 = csub(z0, z2);
    float2 E1 = make_float2(z1.x + z3.y, z1.y - z3.x);
    float2 E3 = make_float2(z1.x - z3.y, z1.y + z3.x);
    float2 u0 = cadd(a[1], a[5]), u1 = csub(a[1], a[5]);
    float2 u2 = cadd(a[3], a[7]), u3 = csub(a[3], a[7]);
    float2 O0 = cadd(u0, u2), O2 = csub(u0, u2);
    float2 O1 = make_float2(u1.x + u3.y, u1.y - u3.x);
    float2 O3 = make_float2(u1.x - u3.y, u1.y + u3.x);
    const float s = 0.70710678118654752f;
    float2 T1 = make_float2(s * (O1.x + O1.y), s * (O1.y - O1.x));
    float2 T2 = make_float2(O2.y, -O2.x);
    float2 T3 = make_float2(s * (O3.y - O3.x), -s * (O3.x + O3.y));
    y[0] = cadd(E0, O0); y[4] = csub(E0, O0);
    y[1] = cadd(E1, T1); y[5] = csub(E1, T1);
    y[2] = cadd(E2, T2); y[6] = csub(E2, T2);
    y[3] = cadd(E3, T3); y[7] = csub(E3, T3);
}

// Output position of frequency k (mixed-radix 8,8,4,8 DIF digit reversal)
__device__ __forceinline__ int posk(int k) {
    return ((k >> 8) & 7) | (((k >> 6) & 3) << 3) | (((k >> 3) & 7) << 5) | ((k & 7) << 8);
}

// ---------------------------------------------------------------------------
// Kernel B: TWO packed-real-pair 2048-pt FFTs per block (4 series = one
// float4 column of the (b,t,d) layout). Register mixed-radix 8*8*4*8.
// ---------------------------------------------------------------------------
__global__ void __launch_bounds__(256) k_fft_topk(const float* __restrict__ x) {
    __shared__ float2 X0[2304];        // XP-padded 2048
    __shared__ float2 X1[2304];
    __shared__ float2 cand[64];        // 4 series x 16 candidates {mag, k}
    int tid  = threadIdx.x;
    int lane = tid & 31;
    int b    = blockIdx.x >> 4;
    int dq   = blockIdx.x & 15;        // float4 column: d = 4dq..4dq+3

    // ---- Stage 1: radix-8, stride 256, float4 direct from gmem ----
    {
        float4 v[8];
        const float4* src4 = (const float4*)x + ((size_t)b * NT) * 16 + dq;
#pragma unroll
        for (int m = 0; m < 8; m++) v[m] = src4[(size_t)(tid + (m << 8)) * 16];
        float sw, cw;
        sincospif((float)tid * (1.0f / 1024.0f), &sw, &cw);
        float2 w1 = make_float2(cw, -sw);
        float2 w2 = cmul(w1, w1), w3 = cmul(w2, w1), w4 = cmul(w2, w2);
        float2 w5 = cmul(w3, w2), w6 = cmul(w3, w3), w7 = cmul(w4, w3);
        float2 a[8], y[8];
#pragma unroll
        for (int m = 0; m < 8; m++) a[m] = make_float2(v[m].x, v[m].y);
        dft8(a, y);
        X0[XP(tid)]        = y[0];
        X0[XP(tid + 256)]  = cmul(y[1], w1);
        X0[XP(tid + 512)]  = cmul(y[2], w2);
        X0[XP(tid + 768)]  = cmul(y[3], w3);
        X0[XP(tid + 1024)] = cmul(y[4], w4);
        X0[XP(tid + 1280)] = cmul(y[5], w5);
        X0[XP(tid + 1536)] = cmul(y[6], w6);
        X0[XP(tid + 1792)] = cmul(y[7], w7);
#pragma unroll
        for (int m = 0; m < 8; m++) a[m] = make_float2(v[m].z, v[m].w);
        dft8(a, y);
        X1[XP(tid)]        = y[0];
        X1[XP(tid + 256)]  = cmul(y[1], w1);
        X1[XP(tid + 512)]  = cmul(y[2], w2);
        X1[XP(tid + 768)]  = cmul(y[3], w3);
        X1[XP(tid + 1024)] = cmul(y[4], w4);
        X1[XP(tid + 1280)] = cmul(y[5], w5);
        X1[XP(tid + 1536)] = cmul(y[6], w6);
        X1[XP(tid + 1792)] = cmul(y[7], w7);
    }
    __syncthreads();

    // ---- Stage 2: radix-8, stride 32, within 256-blocks (twiddle shared) ----
    {
        int base = ((tid >> 5) << 8) + lane;
        float sw, cw;
        sincospif((float)lane * (1.0f / 128.0f), &sw, &cw);
        float2 w1 = make_float2(cw, -sw);
        float2 w2 = cmul(w1, w1), w3 = cmul(w2, w1), w4 = cmul(w2, w2);
        float2 w5 = cmul(w3, w2), w6 = cmul(w3, w3), w7 = cmul(w4, w3);
#pragma unroll
        for (int arr = 0; arr < 2; arr++) {
            float2* A = arr ? X1 : X0;
            float2 v[8], y[8];
#pragma unroll
            for (int m = 0; m < 8; m++) v[m] = A[XP(base + (m << 5))];
            dft8(v, y);
            A[XP(base)]       = y[0];
            A[XP(base + 32)]  = cmul(y[1], w1);
            A[XP(base + 64)]  = cmul(y[2], w2);
            A[XP(base + 96)]  = cmul(y[3], w3);
            A[XP(base + 128)] = cmul(y[4], w4);
            A[XP(base + 160)] = cmul(y[5], w5);
            A[XP(base + 192)] = cmul(y[6], w6);
            A[XP(base + 224)] = cmul(y[7], w7);
        }
    }
    __syncthreads();

    // ---- Stage 3: radix-4, stride 8 (twiddle depends on tid&7 only) ----
    {
        float sw, cw;
        sincospif((float)(tid & 7) * (1.0f / 16.0f), &sw, &cw);
        float2 w1 = make_float2(cw, -sw);
        float2 w2 = cmul(w1, w1), w3 = cmul(w2, w1);
#pragma unroll
        for (int arr = 0; arr < 2; arr++) {
            float2* A = arr ? X1 : X0;
#pragma unroll
            for (int n = 0; n < 2; n++) {
                int e = tid + (n << 8);
                int base = ((e >> 3) << 5) + (e & 7);
                float2 a = A[XP(base)], bb = A[XP(base + 8)];
                float2 c = A[XP(base + 16)], d = A[XP(base + 24)];
                float2 z0 = cadd(a, c), z1 = csub(a, c), z2 = cadd(bb, d), z3 = csub(bb, d);
                float2 y0 = cadd(z0, z2), y2 = csub(z0, z2);
                float2 y1 = make_float2(z1.x + z3.y, z1.y - z3.x);
                float2 y3 = make_float2(z1.x - z3.y, z1.y + z3.x);
                A[XP(base)]      = y0;
                A[XP(base + 8)]  = cmul(y1, w1);
                A[XP(base + 16)] = cmul(y2, w2);
                A[XP(base + 24)] = cmul(y3, w3);
            }
        }
    }
    __syncthreads();

    // ---- Stage 4: radix-8 on 8 consecutive (contiguous: XP(8t+q)=9t+q) ----
    {
        int ph = 9 * tid;
#pragma unroll
        for (int arr = 0; arr < 2; arr++) {
            float2* A = arr ? X1 : X0;
            float2 v[8], y[8];
#pragma unroll
            for (int q = 0; q < 8; q++) v[q] = A[ph + q];
            dft8(v, y);
#pragma unroll
            for (int q = 0; q < 8; q++) A[ph + q] = y[q];
        }
    }
    __syncthreads();

    // ---- Top-8 scan: warp w -> series w>>1, half w&1.
    //      k = lane*32 + half*16 + it  => lane drives posk high digits (<=2-way)
    {
        int w      = tid >> 5;
        int series = w >> 1;
        int half   = w & 1;
        int odd    = series & 1;
        const float2* A = (series < 2) ? X0 : X1;
        float bv[KTOP];
        int   bk[KTOP];
#pragma unroll
        for (int q = 0; q < KTOP; q++) { bv[q] = -1.0f; bk[q] = 1; }

#pragma unroll
        for (int it = 0; it < 16; it++) {
            int k = (lane << 5) + (half << 4) + it;
            if (k == 0) continue;
            float2 z1 = A[XP(posk(k))];
            float2 z2 = A[XP(posk(2048 - k))];
            float mg;
            if (odd == 0) {
                float er = z1.x + z2.x, ei = z1.y - z2.y;
                mg = fmaf(er, er, ei * ei);
            } else {
                float orr = z1.y + z2.y, oi = z2.x - z1.x;
                mg = fmaf(orr, orr, oi * oi);
            }
            if (mg > bv[KTOP - 1]) {
                bv[KTOP - 1] = mg; bk[KTOP - 1] = k;
#pragma unroll
                for (int q = KTOP - 1; q > 0; q--) {
                    if (bv[q] > bv[q - 1]) {
                        float tv = bv[q]; bv[q] = bv[q - 1]; bv[q - 1] = tv;
                        int   tk = bk[q]; bk[q] = bk[q - 1]; bk[q - 1] = tk;
                    }
                }
            }
        }

        for (int r = 0; r < KTOP; r++) {
            float v = bv[0];
            int bestl = lane;
#pragma unroll
            for (int off = 16; off; off >>= 1) {
                float ov = __shfl_xor_sync(0xffffffffu, v, off);
                int   ol = __shfl_xor_sync(0xffffffffu, bestl, off);
                if (ov > v || (ov == v && ol < bestl)) { v = ov; bestl = ol; }
            }
            if (lane == bestl) {
                cand[(series << 4) + (half << 3) + r] = make_float2(bv[0], __int_as_float(bk[0]));
#pragma unroll
                for (int q = 0; q < KTOP - 1; q++) { bv[q] = bv[q + 1]; bk[q] = bk[q + 1]; }
                bv[KTOP - 1] = -1.0f;
            }
        }
    }
    __syncthreads();

    // ---- Merge: warp = series, 16 candidates in lanes 0..15 ----
    if (tid < 128) {
        int series = tid >> 5;
        int odd    = series & 1;
        const float2* A = (series < 2) ? X0 : X1;
        float mv = -1.0f;
        int   mk = 1;
        if (lane < 16) {
            float2 cd = cand[(series << 4) + lane];
            mv = cd.x;
            mk = __float_as_int(cd.y);
        }
        int kout = 1;
        for (int r = 0; r < KTOP; r++) {
            float v = mv;
            int bestl = lane;
#pragma unroll
            for (int off = 16; off; off >>= 1) {
                float ov = __shfl_xor_sync(0xffffffffu, v, off);
                int   ol = __shfl_xor_sync(0xffffffffu, bestl, off);
                if (ov > v || (ov == v && ol < bestl)) { v = ov; bestl = ol; }
            }
            int wk = __shfl_sync(0xffffffffu, mk, bestl);
            if (lane == bestl) mv = -1.0f;
            if (lane == r) kout = wk;
        }
        if (lane < KTOP) {
            int k = kout;
            float2 z1 = A[XP(posk(k))];
            float2 z2 = A[XP(posk(2048 - k))];
            float Aa, Bb;
            const float inv = 1.0f / 2048.0f;
            if (odd == 0) { Aa = (z1.x + z2.x) * inv; Bb = (z1.y - z2.y) * inv; }
            else          { Aa = (z1.y + z2.y) * inv; Bb = (z2.x - z1.x) * inv; }
            g_comps[((size_t)(b * ND + 4 * dq + series)) * KTOP + lane] =
                make_float4((float)k, Aa, Bb, 0.0f);
        }
    }
}

// ---------------------------------------------------------------------------
// Kernel C: Chebyshev-recurrence synthesis, 1 d per thread, 8 harmonics,
// seeded per 32-step chunk with sincospif.
// ---------------------------------------------------------------------------
__global__ void __launch_bounds__(128) k_synth(float* __restrict__ out) {
    int tid = threadIdx.x;
    int b   = blockIdx.y;
    int d   = tid & 63;
    int tt0 = (blockIdx.x * 2 + (tid >> 6)) * 32;
    if (tt0 >= OUT_T) return;

    const float4* cp = g_comps + ((size_t)(b * ND + d)) * KTOP;
    float c0[KTOP], c1[KTOP], tc[KTOP];
#pragma unroll
    for (int j = 0; j < KTOP; j++) {
        float4 cc = cp[j];
        int k = (int)cc.x;
        float sw, cw;
        sincospif((float)k * (1.0f / 1024.0f), &sw, &cw);
        float s1, co1;
        sincospif((float)((k * tt0) & 2047) * (1.0f / 1024.0f), &s1, &co1);
        tc[j] = 2.0f * cw;
        c1[j] = cc.y * co1 - cc.z * s1;                    // value at tt0
        float cm = co1 * cw + s1 * sw;                     // cos(th - w)
        float sm = s1 * cw - co1 * sw;                     // sin(th - w)
        c0[j] = cc.y * cm - cc.z * sm;                     // value at tt0-1
    }

    float* op = out + ((size_t)b * OUT_T + tt0) * ND + d;
#pragma unroll
    for (int c = 0; c < 32; c += 2) {
        float s1 = ((c1[0] + c1[1]) + (c1[2] + c1[3])) + ((c1[4] + c1[5]) + (c1[6] + c1[7]));
        op[(size_t)c * ND] = s1;
#pragma unroll
        for (int j = 0; j < KTOP; j++) c0[j] = fmaf(tc[j], c1[j], -c0[j]);
        float s2 = ((c0[0] + c0[1]) + (c0[2] + c0[3])) + ((c0[4] + c0[5]) + (c0[6] + c0[7]));
        op[(size_t)(c + 1) * ND] = s2;
#pragma unroll
        for (int j = 0; j < KTOP; j++) c1[j] = fmaf(tc[j], c0[j], -c1[j]);
    }
}

// Nop kernel: keeps 3 launches/replay so the ncu window stays on k_fft_topk.
__global__ void k_nop() {}

// ---------------------------------------------------------------------------
extern "C" void kernel_launch(void* const* d_in, const int* in_sizes, int n_in,
                              void* d_out, int out_size) {
    const float* x = (const float*)d_in[0];
    float* out = (float*)d_out;

    k_fft_topk<<<NB * 16, 256>>>(x);
    k_synth<<<dim3(34, NB), 128>>>(out);
    k_nop<<<1, 32>>>();
}

// round 8
// speedup vs baseline: 2.5683x; 1.0611x over previous
#include <cuda_runtime.h>
#include <math.h>

#define NT     2048
#define NB     32
#define ND     64
#define OUT_T  2144
#define KTOP   8

// Padding: +1 per 8. <=2-way for all patterns; XP(8t+q) = 9t+q (contiguous).
#define XP(i) ((i) + ((i) >> 3))

// Scratch (allocation-free: __device__ global)
__device__ float4 g_comps[NB * ND * KTOP];     // per-series {k, A, B, 0}

__device__ __forceinline__ float2 cadd(float2 a, float2 b) { return make_float2(a.x + b.x, a.y + b.y); }
__device__ __forceinline__ float2 csub(float2 a, float2 b) { return make_float2(a.x - b.x, a.y - b.y); }
__device__ __forceinline__ float2 cmul(float2 a, float2 b) {
    return make_float2(a.x * b.x - a.y * b.y, a.x * b.y + a.y * b.x);
}
// float4 = two complex numbers (x,y)=(re0,im0), (z,w)=(re1,im1); same twiddle.
__device__ __forceinline__ float4 f4add(float4 a, float4 b) {
    return make_float4(a.x + b.x, a.y + b.y, a.z + b.z, a.w + b.w);
}
__device__ __forceinline__ float4 f4sub(float4 a, float4 b) {
    return make_float4(a.x - b.x, a.y - b.y, a.z - b.z, a.w - b.w);
}
__device__ __forceinline__ float4 cmul4(float4 a, float2 w) {
    return make_float4(a.x * w.x - a.y * w.y, a.x * w.y + a.y * w.x,
                       a.z * w.x - a.w * w.y, a.z * w.y + a.w * w.x);
}

// scalar dft8 (used in stage 1 where halves are processed separately)
__device__ __forceinline__ void dft8(const float2* a, float2* y) {
    float2 z0 = cadd(a[0], a[4]), z1 = csub(a[0], a[4]);
    float2 z2 = cadd(a[2], a[6]), z3 = csub(a[2], a[6]);
    float2 E0 = cadd(z0, z2), E2 = csub(z0, z2);
    float2 E1 = make_float2(z1.x + z3.y, z1.y - z3.x);
    float2 E3 = make_float2(z1.x - z3.y, z1.y + z3.x);
    float2 u0 = cadd(a[1], a[5]), u1 = csub(a[1], a[5]);
    float2 u2 = cadd(a[3], a[7]), u3 = csub(a[3], a[7]);
    float2 O0 = cadd(u0, u2), O2 = csub(u0, u2);
    float2 O1 = make_float2(u1.x + u3.y, u1.y - u3.x);
    float2 O3 = make_float2(u1.x - u3.y, u1.y + u3.x);
    const float s = 0.70710678118654752f;
    float2 T1 = make_float2(s * (O1.x + O1.y), s * (O1.y - O1.x));
    float2 T2 = make_float2(O2.y, -O2.x);
    float2 T3 = make_float2(s * (O3.y - O3.x), -s * (O3.x + O3.y));
    y[0] = cadd(E0, O0); y[4] = csub(E0, O0);
    y[1] = cadd(E1, T1); y[5] = csub(E1, T1);
    y[2] = cadd(E2, T2); y[6] = csub(E2, T2);
    y[3] = cadd(E3, T3); y[7] = csub(E3, T3);
}

// dual (float4) dft8: same butterfly on both complex pairs
__device__ __forceinline__ void dft8_4(const float4* a, float4* y) {
    float4 z0 = f4add(a[0], a[4]), z1 = f4sub(a[0], a[4]);
    float4 z2 = f4add(a[2], a[6]), z3 = f4sub(a[2], a[6]);
    float4 E0 = f4add(z0, z2), E2 = f4sub(z0, z2);
    float4 E1 = make_float4(z1.x + z3.y, z1.y - z3.x, z1.z + z3.w, z1.w - z3.z);
    float4 E3 = make_float4(z1.x - z3.y, z1.y + z3.x, z1.z - z3.w, z1.w + z3.z);
    float4 u0 = f4add(a[1], a[5]), u1 = f4sub(a[1], a[5]);
    float4 u2 = f4add(a[3], a[7]), u3 = f4sub(a[3], a[7]);
    float4 O0 = f4add(u0, u2), O2 = f4sub(u0, u2);
    float4 O1 = make_float4(u1.x + u3.y, u1.y - u3.x, u1.z + u3.w, u1.w - u3.z);
    float4 O3 = make_float4(u1.x - u3.y, u1.y + u3.x, u1.z - u3.w, u1.w + u3.z);
    const float s = 0.70710678118654752f;
    float4 T1 = make_float4(s * (O1.x + O1.y), s * (O1.y - O1.x),
                            s * (O1.z + O1.w), s * (O1.w - O1.z));
    float4 T2 = make_float4(O2.y, -O2.x, O2.w, -O2.z);
    float4 T3 = make_float4(s * (O3.y - O3.x), -s * (O3.x + O3.y),
                            s * (O3.w - O3.z), -s * (O3.z + O3.w));
    y[0] = f4add(E0, O0); y[4] = f4sub(E0, O0);
    y[1] = f4add(E1, T1); y[5] = f4sub(E1, T1);
    y[2] = f4add(E2, T2); y[6] = f4sub(E2, T2);
    y[3] = f4add(E3, T3); y[7] = f4sub(E3, T3);
}

// Output position of frequency k (mixed-radix 8,8,4,8 DIF digit reversal)
__device__ __forceinline__ int posk(int k) {
    return ((k >> 8) & 7) | (((k >> 6) & 3) << 3) | (((k >> 3) & 7) << 5) | ((k & 7) << 8);
}

// ---------------------------------------------------------------------------
// Kernel B: TWO packed-real-pair 2048-pt FFTs per block (4 series = one
// float4 column of (b,t,d)), both complex arrays fused in ONE float4 smem
// array (identical indices -> LDS.128/STS.128, half the smem instructions).
// ---------------------------------------------------------------------------
__global__ void __launch_bounds__(256) k_fft_topk(const float* __restrict__ x) {
    __shared__ float4 X[2304];         // XP-padded 2048, 36 KB
    __shared__ float2 cand[64];        // 4 series x 16 candidates {mag, k}
    int tid  = threadIdx.x;
    int lane = tid & 31;
    int b    = blockIdx.x >> 4;
    int dq   = blockIdx.x & 15;        // float4 column: d = 4dq..4dq+3

    // ---- Stage 1: radix-8, stride 256, float4 from gmem; halves stored
    //      separately via float2 aliasing to bound register pressure ----
    {
        float4 v[8];
        const float4* src4 = (const float4*)x + ((size_t)b * NT) * 16 + dq;
#pragma unroll
        for (int m = 0; m < 8; m++) v[m] = src4[(size_t)(tid + (m << 8)) * 16];
        float sw, cw;
        sincospif((float)tid * (1.0f / 1024.0f), &sw, &cw);
        float2 w1 = make_float2(cw, -sw);
        float2 w2 = cmul(w1, w1), w3 = cmul(w2, w1), w4 = cmul(w2, w2);
        float2 w5 = cmul(w3, w2), w6 = cmul(w3, w3), w7 = cmul(w4, w3);
        float2* Xh = (float2*)X;
        float2 a[8], y[8];
#pragma unroll
        for (int m = 0; m < 8; m++) a[m] = make_float2(v[m].x, v[m].y);
        dft8(a, y);
        Xh[2 * XP(tid)]        = y[0];
        Xh[2 * XP(tid + 256)]  = cmul(y[1], w1);
        Xh[2 * XP(tid + 512)]  = cmul(y[2], w2);
        Xh[2 * XP(tid + 768)]  = cmul(y[3], w3);
        Xh[2 * XP(tid + 1024)] = cmul(y[4], w4);
        Xh[2 * XP(tid + 1280)] = cmul(y[5], w5);
        Xh[2 * XP(tid + 1536)] = cmul(y[6], w6);
        Xh[2 * XP(tid + 1792)] = cmul(y[7], w7);
#pragma unroll
        for (int m = 0; m < 8; m++) a[m] = make_float2(v[m].z, v[m].w);
        dft8(a, y);
        Xh[2 * XP(tid) + 1]        = y[0];
        Xh[2 * XP(tid + 256) + 1]  = cmul(y[1], w1);
        Xh[2 * XP(tid + 512) + 1]  = cmul(y[2], w2);
        Xh[2 * XP(tid + 768) + 1]  = cmul(y[3], w3);
        Xh[2 * XP(tid + 1024) + 1] = cmul(y[4], w4);
        Xh[2 * XP(tid + 1280) + 1] = cmul(y[5], w5);
        Xh[2 * XP(tid + 1536) + 1] = cmul(y[6], w6);
        Xh[2 * XP(tid + 1792) + 1] = cmul(y[7], w7);
    }
    __syncthreads();

    // ---- Stage 2: radix-8, stride 32, within 256-blocks (float4) ----
    {
        int base = ((tid >> 5) << 8) + lane;
        float sw, cw;
        sincospif((float)lane * (1.0f / 128.0f), &sw, &cw);
        float2 w1 = make_float2(cw, -sw);
        float2 w2 = cmul(w1, w1), w3 = cmul(w2, w1), w4 = cmul(w2, w2);
        float2 w5 = cmul(w3, w2), w6 = cmul(w3, w3), w7 = cmul(w4, w3);
        float4 v[8], y[8];
#pragma unroll
        for (int m = 0; m < 8; m++) v[m] = X[XP(base + (m << 5))];
        dft8_4(v, y);
        X[XP(base)]       = y[0];
        X[XP(base + 32)]  = cmul4(y[1], w1);
        X[XP(base + 64)]  = cmul4(y[2], w2);
        X[XP(base + 96)]  = cmul4(y[3], w3);
        X[XP(base + 128)] = cmul4(y[4], w4);
        X[XP(base + 160)] = cmul4(y[5], w5);
        X[XP(base + 192)] = cmul4(y[6], w6);
        X[XP(base + 224)] = cmul4(y[7], w7);
    }
    __syncthreads();

    // ---- Stage 3: radix-4, stride 8 (twiddle depends on tid&7 only) ----
    {
        float sw, cw;
        sincospif((float)(tid & 7) * (1.0f / 16.0f), &sw, &cw);
        float2 w1 = make_float2(cw, -sw);
        float2 w2 = cmul(w1, w1), w3 = cmul(w2, w1);
#pragma unroll
        for (int n = 0; n < 2; n++) {
            int e = tid + (n << 8);
            int base = ((e >> 3) << 5) + (e & 7);
            float4 a = X[XP(base)],      bb = X[XP(base + 8)];
            float4 c = X[XP(base + 16)], d  = X[XP(base + 24)];
            float4 z0 = f4add(a, c), z1 = f4sub(a, c);
            float4 z2 = f4add(bb, d), z3 = f4sub(bb, d);
            float4 y0 = f4add(z0, z2), y2 = f4sub(z0, z2);
            float4 y1 = make_float4(z1.x + z3.y, z1.y - z3.x, z1.z + z3.w, z1.w - z3.z);
            float4 y3 = make_float4(z1.x - z3.y, z1.y + z3.x, z1.z - z3.w, z1.w + z3.z);
            X[XP(base)]      = y0;
            X[XP(base + 8)]  = cmul4(y1, w1);
            X[XP(base + 16)] = cmul4(y2, w2);
            X[XP(base + 24)] = cmul4(y3, w3);
        }
    }
    __syncthreads();

    // ---- Stage 4: radix-8 on 8 consecutive (XP(8t+q) = 9t+q) ----
    {
        int ph = 9 * tid;
        float4 v[8], y[8];
#pragma unroll
        for (int q = 0; q < 8; q++) v[q] = X[ph + q];
        dft8_4(v, y);
#pragma unroll
        for (int q = 0; q < 8; q++) X[ph + q] = y[q];
    }
    __syncthreads();

    // ---- Top-8 scan: warp w -> series w>>1, half w&1.
    //      k = lane*32 + half*16 + it (lane drives posk high digits) ----
    {
        int w      = tid >> 5;
        int series = w >> 1;
        int half   = w & 1;
        int odd    = series & 1;
        int hi     = series >> 1;          // 0 -> (x,y), 1 -> (z,w)
        float bv[KTOP];
        int   bk[KTOP];
#pragma unroll
        for (int q = 0; q < KTOP; q++) { bv[q] = -1.0f; bk[q] = 1; }

#pragma unroll
        for (int it = 0; it < 16; it++) {
            int k = (lane << 5) + (half << 4) + it;
            if (k == 0) continue;
            float4 t1 = X[XP(posk(k))];
            float4 t2 = X[XP(posk(2048 - k))];
            float2 z1 = hi ? make_float2(t1.z, t1.w) : make_float2(t1.x, t1.y);
            float2 z2 = hi ? make_float2(t2.z, t2.w) : make_float2(t2.x, t2.y);
            float mg;
            if (odd == 0) {
                float er = z1.x + z2.x, ei = z1.y - z2.y;
                mg = fmaf(er, er, ei * ei);
            } else {
                float orr = z1.y + z2.y, oi = z2.x - z1.x;
                mg = fmaf(orr, orr, oi * oi);
            }
            if (mg > bv[KTOP - 1]) {
                bv[KTOP - 1] = mg; bk[KTOP - 1] = k;
#pragma unroll
                for (int q = KTOP - 1; q > 0; q--) {
                    if (bv[q] > bv[q - 1]) {
                        float tv = bv[q]; bv[q] = bv[q - 1]; bv[q - 1] = tv;
                        int   tk = bk[q]; bk[q] = bk[q - 1]; bk[q - 1] = tk;
                    }
                }
            }
        }

        for (int r = 0; r < KTOP; r++) {
            float v = bv[0];
            int bestl = lane;
#pragma unroll
            for (int off = 16; off; off >>= 1) {
                float ov = __shfl_xor_sync(0xffffffffu, v, off);
                int   ol = __shfl_xor_sync(0xffffffffu, bestl, off);
                if (ov > v || (ov == v && ol < bestl)) { v = ov; bestl = ol; }
            }
            if (lane == bestl) {
                cand[(series << 4) + (half << 3) + r] = make_float2(bv[0], __int_as_float(bk[0]));
#pragma unroll
                for (int q = 0; q < KTOP - 1; q++) { bv[q] = bv[q + 1]; bk[q] = bk[q + 1]; }
                bv[KTOP - 1] = -1.0f;
            }
        }
    }
    __syncthreads();

    // ---- Merge: warp = series, 16 candidates in lanes 0..15 ----
    if (tid < 128) {
        int series = tid >> 5;
        int odd    = series & 1;
        int hi     = series >> 1;
        float mv = -1.0f;
        int   mk = 1;
        if (lane < 16) {
            float2 cd = cand[(series << 4) + lane];
            mv = cd.x;
            mk = __float_as_int(cd.y);
        }
        int kout = 1;
        for (int r = 0; r < KTOP; r++) {
            float v = mv;
            int bestl = lane;
#pragma unroll
            for (int off = 16; off; off >>= 1) {
                float ov = __shfl_xor_sync(0xffffffffu, v, off);
                int   ol = __shfl_xor_sync(0xffffffffu, bestl, off);
                if (ov > v || (ov == v && ol < bestl)) { v = ov; bestl = ol; }
            }
            int wk = __shfl_sync(0xffffffffu, mk, bestl);
            if (lane == bestl) mv = -1.0f;
            if (lane == r) kout = wk;
        }
        if (lane < KTOP) {
            int k = kout;
            float4 t1 = X[XP(posk(k))];
            float4 t2 = X[XP(posk(2048 - k))];
            float2 z1 = hi ? make_float2(t1.z, t1.w) : make_float2(t1.x, t1.y);
            float2 z2 = hi ? make_float2(t2.z, t2.w) : make_float2(t2.x, t2.y);
            float Aa, Bb;
            const float inv = 1.0f / 2048.0f;
            if (odd == 0) { Aa = (z1.x + z2.x) * inv; Bb = (z1.y - z2.y) * inv; }
            else          { Aa = (z1.y + z2.y) * inv; Bb = (z2.x - z1.x) * inv; }
            g_comps[((size_t)(b * ND + 4 * dq + series)) * KTOP + lane] =
                make_float4((float)k, Aa, Bb, 0.0f);
        }
    }
}

// ---------------------------------------------------------------------------
// Kernel C: Chebyshev-recurrence synthesis, 1 d per thread, 8 harmonics,
// seeded per 32-step chunk with sincospif.
// ---------------------------------------------------------------------------
__global__ void __launch_bounds__(128) k_synth(float* __restrict__ out) {
    int tid = threadIdx.x;
    int b   = blockIdx.y;
    int d   = tid & 63;
    int tt0 = (blockIdx.x * 2 + (tid >> 6)) * 32;
    if (tt0 >= OUT_T) return;

    const float4* cp = g_comps + ((size_t)(b * ND + d)) * KTOP;
    float c0[KTOP], c1[KTOP], tc[KTOP];
#pragma unroll
    for (int j = 0; j < KTOP; j++) {
        float4 cc = cp[j];
        int k = (int)cc.x;
        float sw, cw;
        sincospif((float)k * (1.0f / 1024.0f), &sw, &cw);
        float s1, co1;
        sincospif((float)((k * tt0) & 2047) * (1.0f / 1024.0f), &s1, &co1);
        tc[j] = 2.0f * cw;
        c1[j] = cc.y * co1 - cc.z * s1;                    // value at tt0
        float cm = co1 * cw + s1 * sw;                     // cos(th - w)
        float sm = s1 * cw - co1 * sw;                     // sin(th - w)
        c0[j] = cc.y * cm - cc.z * sm;                     // value at tt0-1
    }

    float* op = out + ((size_t)b * OUT_T + tt0) * ND + d;
#pragma unroll
    for (int c = 0; c < 32; c += 2) {
        float s1 = ((c1[0] + c1[1]) + (c1[2] + c1[3])) + ((c1[4] + c1[5]) + (c1[6] + c1[7]));
        op[(size_t)c * ND] = s1;
#pragma unroll
        for (int j = 0; j < KTOP; j++) c0[j] = fmaf(tc[j], c1[j], -c0[j]);
        float s2 = ((c0[0] + c0[1]) + (c0[2] + c0[3])) + ((c0[4] + c0[5]) + (c0[6] + c0[7]));
        op[(size_t)(c + 1) * ND] = s2;
#pragma unroll
        for (int j = 0; j < KTOP; j++) c1[j] = fmaf(tc[j], c0[j], -c1[j]);
    }
}

// ---------------------------------------------------------------------------
extern "C" void kernel_launch(void* const* d_in, const int* in_sizes, int n_in,
                              void* d_out, int out_size) {
    const float* x = (const float*)d_in[0];
    float* out = (float*)d_out;

    k_fft_topk<<<NB * 16, 256>>>(x);
    k_synth<<<dim3(34, NB), 128>>>(out);
}

// round 9
// speedup vs baseline: 2.7608x; 1.0749x over previous
#include <cuda_runtime.h>
#include <math.h>

#define NT     2048
#define NB     32
#define ND     64
#define OUT_T  2144
#define KTOP   8

// Padding: +1 per 8. <=2-way for all patterns; XP(8t+q) = 9t+q (contiguous).
#define XP(i) ((i) + ((i) >> 3))
// Mag-buffer padding: +1 per 32 (kills stride-32 write conflicts)
#define MP(i) ((i) + ((i) >> 5))

// Scratch (allocation-free: __device__ global)
__device__ float4 g_comps[NB * ND * KTOP];     // per-series {k, A, B, 0}

__device__ __forceinline__ float2 cadd(float2 a, float2 b) { return make_float2(a.x + b.x, a.y + b.y); }
__device__ __forceinline__ float2 csub(float2 a, float2 b) { return make_float2(a.x - b.x, a.y - b.y); }
__device__ __forceinline__ float2 cmul(float2 a, float2 b) {
    return make_float2(a.x * b.x - a.y * b.y, a.x * b.y + a.y * b.x);
}
__device__ __forceinline__ float4 f4add(float4 a, float4 b) {
    return make_float4(a.x + b.x, a.y + b.y, a.z + b.z, a.w + b.w);
}
__device__ __forceinline__ float4 f4sub(float4 a, float4 b) {
    return make_float4(a.x - b.x, a.y - b.y, a.z - b.z, a.w - b.w);
}
__device__ __forceinline__ float4 cmul4(float4 a, float2 w) {
    return make_float4(a.x * w.x - a.y * w.y, a.x * w.y + a.y * w.x,
                       a.z * w.x - a.w * w.y, a.z * w.y + a.w * w.x);
}
// pack two twiddled complex halves into one float4
__device__ __forceinline__ float4 pk(float2 lo, float2 hi, float2 w) {
    float2 a = cmul(lo, w), b = cmul(hi, w);
    return make_float4(a.x, a.y, b.x, b.y);
}

// scalar dft8
__device__ __forceinline__ void dft8(const float2* a, float2* y) {
    float2 z0 = cadd(a[0], a[4]), z1 = csub(a[0], a[4]);
    float2 z2 = cadd(a[2], a[6]), z3 = csub(a[2], a[6]);
    float2 E0 = cadd(z0, z2), E2 = csub(z0, z2);
    float2 E1 = make_float2(z1.x + z3.y, z1.y - z3.x);
    float2 E3 = make_float2(z1.x - z3.y, z1.y + z3.x);
    float2 u0 = cadd(a[1], a[5]), u1 = csub(a[1], a[5]);
    float2 u2 = cadd(a[3], a[7]), u3 = csub(a[3], a[7]);
    float2 O0 = cadd(u0, u2), O2 = csub(u0, u2);
    float2 O1 = make_float2(u1.x + u3.y, u1.y - u3.x);
    float2 O3 = make_float2(u1.x - u3.y, u1.y + u3.x);
    const float s = 0.70710678118654752f;
    float2 T1 = make_float2(s * (O1.x + O1.y), s * (O1.y - O1.x));
    float2 T2 = make_float2(O2.y, -O2.x);
    float2 T3 = make_float2(s * (O3.y - O3.x), -s * (O3.x + O3.y));
    y[0] = cadd(E0, O0); y[4] = csub(E0, O0);
    y[1] = cadd(E1, T1); y[5] = csub(E1, T1);
    y[2] = cadd(E2, T2); y[6] = csub(E2, T2);
    y[3] = cadd(E3, T3); y[7] = csub(E3, T3);
}

// dual (float4) dft8
__device__ __forceinline__ void dft8_4(const float4* a, float4* y) {
    float4 z0 = f4add(a[0], a[4]), z1 = f4sub(a[0], a[4]);
    float4 z2 = f4add(a[2], a[6]), z3 = f4sub(a[2], a[6]);
    float4 E0 = f4add(z0, z2), E2 = f4sub(z0, z2);
    float4 E1 = make_float4(z1.x + z3.y, z1.y - z3.x, z1.z + z3.w, z1.w - z3.z);
    float4 E3 = make_float4(z1.x - z3.y, z1.y + z3.x, z1.z - z3.w, z1.w + z3.z);
    float4 u0 = f4add(a[1], a[5]), u1 = f4sub(a[1], a[5]);
    float4 u2 = f4add(a[3], a[7]), u3 = f4sub(a[3], a[7]);
    float4 O0 = f4add(u0, u2), O2 = f4sub(u0, u2);
    float4 O1 = make_float4(u1.x + u3.y, u1.y - u3.x, u1.z + u3.w, u1.w - u3.z);
    float4 O3 = make_float4(u1.x - u3.y, u1.y + u3.x, u1.z - u3.w, u1.w + u3.z);
    const float s = 0.70710678118654752f;
    float4 T1 = make_float4(s * (O1.x + O1.y), s * (O1.y - O1.x),
                            s * (O1.z + O1.w), s * (O1.w - O1.z));
    float4 T2 = make_float4(O2.y, -O2.x, O2.w, -O2.z);
    float4 T3 = make_float4(s * (O3.y - O3.x), -s * (O3.x + O3.y),
                            s * (O3.w - O3.z), -s * (O3.z + O3.w));
    y[0] = f4add(E0, O0); y[4] = f4sub(E0, O0);
    y[1] = f4add(E1, T1); y[5] = f4sub(E1, T1);
    y[2] = f4add(E2, T2); y[6] = f4sub(E2, T2);
    y[3] = f4add(E3, T3); y[7] = f4sub(E3, T3);
}

// Output position of frequency k (mixed-radix 8,8,4,8 DIF digit reversal)
__device__ __forceinline__ int posk(int k) {
    return ((k >> 8) & 7) | (((k >> 6) & 3) << 3) | (((k >> 3) & 7) << 5) | ((k & 7) << 8);
}

// ---------------------------------------------------------------------------
// Kernel B: TWO packed-real-pair 2048-pt FFTs per block (4 series = one
// float4 column of (b,t,d)) in one fused float4 smem array; magnitude
// pre-pass + conflict-free compact top-8 scan.
// ---------------------------------------------------------------------------
__global__ void __launch_bounds__(256) k_fft_topk(const float* __restrict__ x) {
    __shared__ float4 X[2304];          // XP-padded 2048, 36 KB
    __shared__ float2 M2[1056];         // MP-padded 1024 mags, 8.25 KB
    __shared__ float2 cand[128];        // 4 series x 32 candidates {mag, k}
    int tid  = threadIdx.x;
    int lane = tid & 31;
    int wid  = tid >> 5;
    int b    = blockIdx.x >> 4;
    int dq   = blockIdx.x & 15;         // float4 column: d = 4dq..4dq+3

    // ---- Stage 1: radix-8, stride 256, float4 from gmem; packed stores ----
    {
        float4 v[8];
        const float4* src4 = (const float4*)x + ((size_t)b * NT) * 16 + dq;
#pragma unroll
        for (int m = 0; m < 8; m++) v[m] = src4[(size_t)(tid + (m << 8)) * 16];
        float sw, cw;
        sincospif((float)tid * (1.0f / 1024.0f), &sw, &cw);
        float2 w1 = make_float2(cw, -sw);
        float2 w2 = cmul(w1, w1), w3 = cmul(w2, w1), w4 = cmul(w2, w2);
        float2 w5 = cmul(w3, w2), w6 = cmul(w3, w3), w7 = cmul(w4, w3);
        float2 a[8], lo[8], hi[8];
#pragma unroll
        for (int m = 0; m < 8; m++) a[m] = make_float2(v[m].x, v[m].y);
        dft8(a, lo);
#pragma unroll
        for (int m = 0; m < 8; m++) a[m] = make_float2(v[m].z, v[m].w);
        dft8(a, hi);
        X[XP(tid)]        = make_float4(lo[0].x, lo[0].y, hi[0].x, hi[0].y);
        X[XP(tid + 256)]  = pk(lo[1], hi[1], w1);
        X[XP(tid + 512)]  = pk(lo[2], hi[2], w2);
        X[XP(tid + 768)]  = pk(lo[3], hi[3], w3);
        X[XP(tid + 1024)] = pk(lo[4], hi[4], w4);
        X[XP(tid + 1280)] = pk(lo[5], hi[5], w5);
        X[XP(tid + 1536)] = pk(lo[6], hi[6], w6);
        X[XP(tid + 1792)] = pk(lo[7], hi[7], w7);
    }
    __syncthreads();

    // ---- Stage 2: radix-8, stride 32, within 256-blocks (float4) ----
    {
        int base = (wid << 8) + lane;
        float sw, cw;
        sincospif((float)lane * (1.0f / 128.0f), &sw, &cw);
        float2 w1 = make_float2(cw, -sw);
        float2 w2 = cmul(w1, w1), w3 = cmul(w2, w1), w4 = cmul(w2, w2);
        float2 w5 = cmul(w3, w2), w6 = cmul(w3, w3), w7 = cmul(w4, w3);
        float4 v[8], y[8];
#pragma unroll
        for (int m = 0; m < 8; m++) v[m] = X[XP(base + (m << 5))];
        dft8_4(v, y);
        X[XP(base)]       = y[0];
        X[XP(base + 32)]  = cmul4(y[1], w1);
        X[XP(base + 64)]  = cmul4(y[2], w2);
        X[XP(base + 96)]  = cmul4(y[3], w3);
        X[XP(base + 128)] = cmul4(y[4], w4);
        X[XP(base + 160)] = cmul4(y[5], w5);
        X[XP(base + 192)] = cmul4(y[6], w6);
        X[XP(base + 224)] = cmul4(y[7], w7);
    }
    __syncthreads();

    // ---- Stage 3: radix-4, stride 8 (twiddle depends on tid&7 only) ----
    {
        float sw, cw;
        sincospif((float)(tid & 7) * (1.0f / 16.0f), &sw, &cw);
        float2 w1 = make_float2(cw, -sw);
        float2 w2 = cmul(w1, w1), w3 = cmul(w2, w1);
#pragma unroll
        for (int n = 0; n < 2; n++) {
            int e = tid + (n << 8);
            int base = ((e >> 3) << 5) + (e & 7);
            float4 a = X[XP(base)],      bb = X[XP(base + 8)];
            float4 c = X[XP(base + 16)], d  = X[XP(base + 24)];
            float4 z0 = f4add(a, c), z1 = f4sub(a, c);
            float4 z2 = f4add(bb, d), z3 = f4sub(bb, d);
            float4 y0 = f4add(z0, z2), y2 = f4sub(z0, z2);
            float4 y1 = make_float4(z1.x + z3.y, z1.y - z3.x, z1.z + z3.w, z1.w - z3.z);
            float4 y3 = make_float4(z1.x - z3.y, z1.y + z3.x, z1.z - z3.w, z1.w + z3.z);
            X[XP(base)]      = y0;
            X[XP(base + 8)]  = cmul4(y1, w1);
            X[XP(base + 16)] = cmul4(y2, w2);
            X[XP(base + 24)] = cmul4(y3, w3);
        }
    }
    __syncthreads();

    // ---- Stage 4: radix-8 on 8 consecutive (XP(8t+q) = 9t+q) ----
    {
        int ph = 9 * tid;
        float4 v[8], y[8];
#pragma unroll
        for (int q = 0; q < 8; q++) v[q] = X[ph + q];
        dft8_4(v, y);
#pragma unroll
        for (int q = 0; q < 8; q++) X[ph + q] = y[q];
    }
    __syncthreads();

    // ---- Top-8 via magnitude pre-pass: pass p=0 -> series 0,1 (lo),
    //      pass p=1 -> series 2,3 (hi). ----
#pragma unroll
    for (int p = 0; p < 2; p++) {
        // (a) magnitudes for all k in 1..1023 (lane drives posk's high digits)
#pragma unroll
        for (int q = 0; q < 4; q++) {
            int k = (lane << 5) | (wid << 2) | q;
            float2 m2;
            if (k == 0) {
                m2 = make_float2(-1.0f, -1.0f);
            } else {
                float4 t1 = X[XP(posk(k))];
                float4 t2 = X[XP(posk(2048 - k))];
                float ar = p ? t1.z : t1.x, ai = p ? t1.w : t1.y;
                float br = p ? t2.z : t2.x, bi = p ? t2.w : t2.y;
                float er  = ar + br, ei = ai - bi;    // even-d series of the pair
                float orr = ai + bi, oi = br - ar;    // odd-d series of the pair
                m2 = make_float2(fmaf(er, er, ei * ei), fmaf(orr, orr, oi * oi));
            }
            M2[MP(k)] = m2;
        }
        __syncthreads();

        // (b) scan: warp w -> local series w>>2, quarter w&3; consecutive k
        {
            int local   = wid >> 2;             // 0 or 1
            int quarter = wid & 3;
            int series  = p * 2 + local;
            float bv[KTOP];
            int   bk[KTOP];
#pragma unroll
            for (int q = 0; q < KTOP; q++) { bv[q] = -1.0f; bk[q] = 1; }
#pragma unroll
            for (int it = 0; it < 8; it++) {
                int k = (quarter << 8) | (it << 5) | lane;
                float2 m2 = M2[MP(k)];
                float mg = local ? m2.y : m2.x;   // k==0 slot holds -1
                if (mg > bv[KTOP - 1]) {
                    bv[KTOP - 1] = mg; bk[KTOP - 1] = k;
#pragma unroll
                    for (int q = KTOP - 1; q > 0; q--) {
                        if (bv[q] > bv[q - 1]) {
                            float tv = bv[q]; bv[q] = bv[q - 1]; bv[q - 1] = tv;
                            int   tk = bk[q]; bk[q] = bk[q - 1]; bk[q - 1] = tk;
                        }
                    }
                }
            }
            for (int r = 0; r < KTOP; r++) {
                float v = bv[0];
                int bestl = lane;
#pragma unroll
                for (int off = 16; off; off >>= 1) {
                    float ov = __shfl_xor_sync(0xffffffffu, v, off);
                    int   ol = __shfl_xor_sync(0xffffffffu, bestl, off);
                    if (ov > v || (ov == v && ol < bestl)) { v = ov; bestl = ol; }
                }
                if (lane == bestl) {
                    cand[(series << 5) + (quarter << 3) + r] =
                        make_float2(bv[0], __int_as_float(bk[0]));
#pragma unroll
                    for (int q = 0; q < KTOP - 1; q++) { bv[q] = bv[q + 1]; bk[q] = bk[q + 1]; }
                    bv[KTOP - 1] = -1.0f;
                }
            }
        }
        __syncthreads();
    }

    // ---- Merge: warp = series, 32 candidates ----
    if (tid < 128) {
        int series = wid;
        int odd    = series & 1;
        int hi     = series >> 1;
        float2 cd = cand[(series << 5) + lane];
        float mv = cd.x;
        int   mk = __float_as_int(cd.y);
        int kout = 1;
        for (int r = 0; r < KTOP; r++) {
            float v = mv;
            int bestl = lane;
#pragma unroll
            for (int off = 16; off; off >>= 1) {
                float ov = __shfl_xor_sync(0xffffffffu, v, off);
                int   ol = __shfl_xor_sync(0xffffffffu, bestl, off);
                if (ov > v || (ov == v && ol < bestl)) { v = ov; bestl = ol; }
            }
            int wk = __shfl_sync(0xffffffffu, mk, bestl);
            if (lane == bestl) mv = -1.0f;
            if (lane == r) kout = wk;
        }
        if (lane < KTOP) {
            int k = kout;
            float4 t1 = X[XP(posk(k))];
            float4 t2 = X[XP(posk(2048 - k))];
            float2 z1 = hi ? make_float2(t1.z, t1.w) : make_float2(t1.x, t1.y);
            float2 z2 = hi ? make_float2(t2.z, t2.w) : make_float2(t2.x, t2.y);
            float Aa, Bb;
            const float inv = 1.0f / 2048.0f;
            if (odd == 0) { Aa = (z1.x + z2.x) * inv; Bb = (z1.y - z2.y) * inv; }
            else          { Aa = (z1.y + z2.y) * inv; Bb = (z2.x - z1.x) * inv; }
            g_comps[((size_t)(b * ND + 4 * dq + series)) * KTOP + lane] =
                make_float4((float)k, Aa, Bb, 0.0f);
        }
    }
}

// ---------------------------------------------------------------------------
// Kernel C: Chebyshev-recurrence synthesis, 1 d per thread, 8 harmonics,
// 67-step chunks (2144 = 32 x 67) to amortize the sincospif seeding.
// ---------------------------------------------------------------------------
__global__ void __launch_bounds__(128) k_synth(float* __restrict__ out) {
    int tid   = threadIdx.x;
    int b     = blockIdx.y;
    int d     = tid & 63;
    int chunk = blockIdx.x * 2 + (tid >> 6);   // 0..31
    int tt0   = chunk * 67;

    const float4* cp = g_comps + ((size_t)(b * ND + d)) * KTOP;
    float c0[KTOP], c1[KTOP], tc[KTOP];
#pragma unroll
    for (int j = 0; j < KTOP; j++) {
        float4 cc = cp[j];
        int k = (int)cc.x;
        float sw, cw;
        sincospif((float)k * (1.0f / 1024.0f), &sw, &cw);
        float s1, co1;
        sincospif((float)((k * tt0) & 2047) * (1.0f / 1024.0f), &s1, &co1);
        tc[j] = 2.0f * cw;
        c1[j] = cc.y * co1 - cc.z * s1;                    // value at tt0
        float cm = co1 * cw + s1 * sw;                     // cos(th - w)
        float sm = s1 * cw - co1 * sw;                     // sin(th - w)
        c0[j] = cc.y * cm - cc.z * sm;                     // value at tt0-1
    }

    float* op = out + ((size_t)b * OUT_T + tt0) * ND + d;
#pragma unroll
    for (int c = 0; c < 66; c += 2) {
        float s1 = ((c1[0] + c1[1]) + (c1[2] + c1[3])) + ((c1[4] + c1[5]) + (c1[6] + c1[7]));
        op[(size_t)c * ND] = s1;
#pragma unroll
        for (int j = 0; j < KTOP; j++) c0[j] = fmaf(tc[j], c1[j], -c0[j]);
        float s2 = ((c0[0] + c0[1]) + (c0[2] + c0[3])) + ((c0[4] + c0[5]) + (c0[6] + c0[7]));
        op[(size_t)(c + 1) * ND] = s2;
#pragma unroll
        for (int j = 0; j < KTOP; j++) c1[j] = fmaf(tc[j], c0[j], -c1[j]);
    }
    // final step (c = 66): c1 holds value at tt0+66
    float sl = ((c1[0] + c1[1]) + (c1[2] + c1[3])) + ((c1[4] + c1[5]) + (c1[6] + c1[7]));
    op[(size_t)66 * ND] = sl;
}

// ---------------------------------------------------------------------------
extern "C" void kernel_launch(void* const* d_in, const int* in_sizes, int n_in,
                              void* d_out, int out_size) {
    const float* x = (const float*)d_in[0];
    float* out = (float*)d_out;

    k_fft_topk<<<NB * 16, 256>>>(x);
    k_synth<<<dim3(16, NB), 128>>>(out);
}